// round 1
// baseline (speedup 1.0000x reference)
#include <cuda_runtime.h>

#define BB 64
#define NN 2048
#define DD 512
#define KK 64
#define KGC 80

// Scratch (device globals — no allocation allowed)
__device__ float g_assign[BB * NN * KK];   // 32 MB
__device__ float g_vlad[BB * DD * KK];     // 8 MB
__device__ float g_asum[BB * KK];
__device__ float g_norm2[BB * KK];
__device__ float g_scale[BB * KK];

// Packed fp32x2 FMA (SASS FFMA2) — 2x fp32 throughput, exact fp32 rounding
#define FMA2(d, a, b) asm("fma.rn.f32x2 %0, %1, %2, %0;" : "+l"(d) : "l"(a), "l"(b))

__device__ __forceinline__ unsigned long long dup2(float v) {
    unsigned int b = __float_as_uint(v);
    return (unsigned long long)b * 0x100000001ULL;
}
__device__ __forceinline__ float lo32(unsigned long long v) {
    return __uint_as_float((unsigned int)(v & 0xffffffffULL));
}
__device__ __forceinline__ float hi32(unsigned long long v) {
    return __uint_as_float((unsigned int)(v >> 32));
}

// ---------------------------------------------------------------------------
// Kernel 0: zero accumulators (graph replays must start clean)
// ---------------------------------------------------------------------------
__global__ void k_zero() {
    int i = blockIdx.x * 256 + threadIdx.x;
    if (i < BB * KK) { g_asum[i] = 0.0f; g_norm2[i] = 0.0f; }
}

// ---------------------------------------------------------------------------
// Kernel 1: logits GEMM + BN affine + softmax(80) + assignment + a_sum
// Block: 256 threads, tile 128 rows x 80 cols. Thread: 8 rows (4 f32x2 pairs)
// x 5 cols. Clusters staged in smem as duplicated pairs for FFMA2 broadcast.
// ---------------------------------------------------------------------------
__global__ __launch_bounds__(256) void k_logits(
    const float* __restrict__ x, const float* __restrict__ clusters,
    const float* __restrict__ bnw, const float* __restrict__ bnb,
    const float* __restrict__ rm, const float* __restrict__ rv)
{
    __shared__ __align__(16) float sX[32][132];               // [d][row], padded
    __shared__ __align__(16) unsigned long long sC[32][KGC];  // dup pairs [d][col]
    __shared__ float sRed[16][KGC];

    const int tid = threadIdx.x;
    const int tx = tid & 15;       // col group (5 cols each)
    const int ty = tid >> 4;       // row group (8 rows each)
    const int b = blockIdx.y;
    const int n0 = blockIdx.x * 128;
    const float* xb = x + (size_t)b * NN * DD;

    unsigned long long acc[4][5];
    #pragma unroll
    for (int p = 0; p < 4; p++)
        #pragma unroll
        for (int j = 0; j < 5; j++) acc[p][j] = 0ULL;

    for (int dt = 0; dt < DD / 32; dt++) {
        // load x tile transposed into sX[d][row]
        {
            const int dq = tid & 7;
            const int rb = tid >> 3;
            #pragma unroll
            for (int i = 0; i < 4; i++) {
                int r = rb + i * 32;
                float4 v = *(const float4*)&xb[(size_t)(n0 + r) * DD + dt * 32 + dq * 4];
                sX[dq * 4 + 0][r] = v.x; sX[dq * 4 + 1][r] = v.y;
                sX[dq * 4 + 2][r] = v.z; sX[dq * 4 + 3][r] = v.w;
            }
        }
        // load clusters tile as duplicated pairs
        #pragma unroll
        for (int j = 0; j < 10; j++) {
            int idx = tid + j * 256;          // 0..2559
            int d = idx / KGC, c = idx - d * KGC;
            sC[d][c] = dup2(clusters[(size_t)(dt * 32 + d) * KGC + c]);
        }
        __syncthreads();

        #pragma unroll 4
        for (int d = 0; d < 32; d++) {
            ulonglong2 A0 = *(const ulonglong2*)&sX[d][ty * 8];
            ulonglong2 A1 = *(const ulonglong2*)&sX[d][ty * 8 + 4];
            unsigned long long Ap[4] = {A0.x, A0.y, A1.x, A1.y};
            unsigned long long Bv[5];
            #pragma unroll
            for (int j = 0; j < 5; j++) Bv[j] = sC[d][tx * 5 + j];
            #pragma unroll
            for (int p = 0; p < 4; p++)
                #pragma unroll
                for (int j = 0; j < 5; j++) FMA2(acc[p][j], Ap[p], Bv[j]);
        }
        __syncthreads();
    }

    // BN affine params for my 5 columns
    float scj[5], rmj[5], bbj[5];
    #pragma unroll
    for (int j = 0; j < 5; j++) {
        int c = tx * 5 + j;
        scj[j] = bnw[c] * rsqrtf(rv[c] + 1e-5f);
        rmj[j] = rm[c];
        bbj[j] = bnb[c];
    }

    float colsum[5] = {0.f, 0.f, 0.f, 0.f, 0.f};
    #pragma unroll
    for (int i = 0; i < 8; i++) {
        int p = i >> 1;
        float l[5];
        #pragma unroll
        for (int j = 0; j < 5; j++) {
            float f = (i & 1) ? hi32(acc[p][j]) : lo32(acc[p][j]);
            l[j] = (f - rmj[j]) * scj[j] + bbj[j];
        }
        // softmax over 80 cols: 16 threads (same ty half-warp) hold one row
        float m = l[0];
        #pragma unroll
        for (int j = 1; j < 5; j++) m = fmaxf(m, l[j]);
        #pragma unroll
        for (int o = 8; o >= 1; o >>= 1) m = fmaxf(m, __shfl_xor_sync(0xffffffffu, m, o));
        float s = 0.f;
        #pragma unroll
        for (int j = 0; j < 5; j++) { l[j] = expf(l[j] - m); s += l[j]; }
        #pragma unroll
        for (int o = 8; o >= 1; o >>= 1) s += __shfl_xor_sync(0xffffffffu, s, o);
        float inv = 1.0f / s;

        int r = n0 + ty * 8 + i;
        float* arow = &g_assign[((size_t)b * NN + r) * KK];
        #pragma unroll
        for (int j = 0; j < 5; j++) {
            int c = tx * 5 + j;
            if (c < KK) {
                float a = l[j] * inv;
                arow[c] = a;
                colsum[j] += a;
            }
        }
    }

    // reduce colsum over the 16 ty groups -> a_sum
    #pragma unroll
    for (int j = 0; j < 5; j++) sRed[ty][tx * 5 + j] = colsum[j];
    __syncthreads();
    if (tid < KK) {
        float s = 0.f;
        #pragma unroll
        for (int t = 0; t < 16; t++) s += sRed[t][tid];
        atomicAdd(&g_asum[b * KK + tid], s);
    }
}

// ---------------------------------------------------------------------------
// Kernel 2: vlad[b,d,k] = sum_n x[b,n,d]*assign[b,n,k] - a_sum[b,k]*c2[d,k]
// Block: 128 threads, tile 128 d x 64 k for one batch; loops over all n.
// Thread: 8 d (4 f32x2 pairs) x 8 k. Also accumulates per-(b,k) norm^2.
// ---------------------------------------------------------------------------
__global__ __launch_bounds__(128) void k_vlad(
    const float* __restrict__ x, const float* __restrict__ clusters2)
{
    __shared__ __align__(16) float sXv[32][128];              // [n][d]
    __shared__ __align__(16) unsigned long long sA[32][KK];   // dup pairs [n][k]
    __shared__ float sRed[16][KK];

    const int tid = threadIdx.x;
    const int tx = tid & 7;      // k group (8 k each)
    const int ty = tid >> 3;     // d group (8 d each), 0..15
    const int b = blockIdx.y;
    const int d0 = blockIdx.x * 128;
    const float* xb = x + (size_t)b * NN * DD;
    const float* ab = g_assign + (size_t)b * NN * KK;

    unsigned long long acc[4][8];
    #pragma unroll
    for (int p = 0; p < 4; p++)
        #pragma unroll
        for (int q = 0; q < 8; q++) acc[p][q] = 0ULL;

    for (int nt = 0; nt < NN / 32; nt++) {
        {
            const int dq = tid & 31;
            const int nb_ = tid >> 5;
            #pragma unroll
            for (int i = 0; i < 8; i++) {
                int n = nb_ + i * 4;
                float4 v = *(const float4*)&xb[(size_t)(nt * 32 + n) * DD + d0 + dq * 4];
                *(float4*)&sXv[n][dq * 4] = v;
            }
        }
        #pragma unroll
        for (int j = 0; j < 16; j++) {
            int idx = tid + j * 128;
            int n = idx >> 6, k = idx & 63;
            sA[n][k] = dup2(ab[(size_t)(nt * 32 + n) * KK + k]);
        }
        __syncthreads();

        #pragma unroll 4
        for (int n = 0; n < 32; n++) {
            ulonglong2 X0 = *(const ulonglong2*)&sXv[n][ty * 8];
            ulonglong2 X1 = *(const ulonglong2*)&sXv[n][ty * 8 + 4];
            unsigned long long Xp[4] = {X0.x, X0.y, X1.x, X1.y};
            unsigned long long Bv[8];
            #pragma unroll
            for (int q = 0; q < 4; q++) {
                ulonglong2 t = *(const ulonglong2*)&sA[n][tx * 8 + q * 2];
                Bv[q * 2] = t.x; Bv[q * 2 + 1] = t.y;
            }
            #pragma unroll
            for (int p = 0; p < 4; p++)
                #pragma unroll
                for (int q = 0; q < 8; q++) FMA2(acc[p][q], Xp[p], Bv[q]);
        }
        __syncthreads();
    }

    // epilogue: subtract a_sum*clusters2, store vlad, accumulate norm^2
    float nrm[8] = {0.f, 0.f, 0.f, 0.f, 0.f, 0.f, 0.f, 0.f};
    float asv[8];
    #pragma unroll
    for (int q = 0; q < 8; q++) asv[q] = g_asum[b * KK + tx * 8 + q];

    #pragma unroll
    for (int p = 0; p < 4; p++) {
        int d_lo = d0 + ty * 8 + 2 * p;
        int d_hi = d_lo + 1;
        #pragma unroll
        for (int q = 0; q < 8; q++) {
            int k = tx * 8 + q;
            float vlo = lo32(acc[p][q]) - asv[q] * clusters2[(size_t)d_lo * KK + k];
            float vhi = hi32(acc[p][q]) - asv[q] * clusters2[(size_t)d_hi * KK + k];
            g_vlad[((size_t)b * DD + d_lo) * KK + k] = vlo;
            g_vlad[((size_t)b * DD + d_hi) * KK + k] = vhi;
            nrm[q] += vlo * vlo + vhi * vhi;
        }
    }
    #pragma unroll
    for (int q = 0; q < 8; q++) sRed[ty][tx * 8 + q] = nrm[q];
    __syncthreads();
    if (tid < KK) {
        float s = 0.f;
        #pragma unroll
        for (int t = 0; t < 16; t++) s += sRed[t][tid];
        atomicAdd(&g_norm2[b * KK + tid], s);
    }
}

// ---------------------------------------------------------------------------
// Kernel 3: per-(b,k) combined scale = 1/max(||col||,eps) * 1/max(||flat||,eps)
// ---------------------------------------------------------------------------
__global__ void k_colscale() {
    int b = blockIdx.x;
    int k = threadIdx.x;   // 64 threads
    float n2 = g_norm2[b * KK + k];
    float nr = sqrtf(n2);
    float inv = 1.0f / fmaxf(nr, 1e-12f);
    float c = n2 * inv * inv;   // 1 if nr>=eps else n2/eps^2 (matches ref exactly)
    __shared__ float sh[2];
    #pragma unroll
    for (int o = 16; o >= 1; o >>= 1) c += __shfl_xor_sync(0xffffffffu, c, o);
    if ((threadIdx.x & 31) == 0) sh[threadIdx.x >> 5] = c;
    __syncthreads();
    float tot = sqrtf(sh[0] + sh[1]);
    float invt = 1.0f / fmaxf(tot, 1e-12f);
    g_scale[b * KK + k] = inv * invt;
}

// ---------------------------------------------------------------------------
// Kernel 4: out[b, d*K+k] = vlad[b,d,k] * scale[b,k]
// ---------------------------------------------------------------------------
__global__ void k_out(float* __restrict__ out) {
    int i = blockIdx.x * 256 + threadIdx.x;  // 2,097,152 total
    int b = i >> 15;
    int k = i & 63;
    out[i] = g_vlad[i] * g_scale[(b << 6) + k];
}

// ---------------------------------------------------------------------------
extern "C" void kernel_launch(void* const* d_in, const int* in_sizes, int n_in,
                              void* d_out, int out_size) {
    const float* x         = (const float*)d_in[0];
    const float* clusters  = (const float*)d_in[1];
    const float* clusters2 = (const float*)d_in[2];
    const float* bnw       = (const float*)d_in[3];
    const float* bnb       = (const float*)d_in[4];
    const float* rm        = (const float*)d_in[5];
    const float* rv        = (const float*)d_in[6];
    float* out = (float*)d_out;

    k_zero<<<(BB * KK + 255) / 256, 256>>>();
    dim3 g1(NN / 128, BB);
    k_logits<<<g1, 256>>>(x, clusters, bnw, bnb, rm, rv);
    dim3 g2(DD / 128, BB);
    k_vlad<<<g2, 128>>>(x, clusters2);
    k_colscale<<<BB, KK>>>();
    k_out<<<(BB * DD * KK) / 256, 256>>>(out);
}

// round 2
// speedup vs baseline: 1.3341x; 1.3341x over previous
#include <cuda_runtime.h>

#define BB 64
#define NN 2048
#define DD 512
#define KK 64
#define KGC 80

// Scratch (device globals — no allocation allowed)
__device__ float g_assign[BB * NN * KK];          // 32 MB
__device__ float g_vpart[4][BB * DD * KK];        // 32 MB (per-n-chunk partials)
__device__ float g_vlad[BB * DD * KK];            // 8 MB
__device__ float g_asum[BB * KK];
__device__ float g_norm2[BB * KK];
__device__ float g_scale[BB * KK];

// Packed fp32x2 FMA (SASS FFMA2) — 2x fp32 throughput, exact fp32 rounding
#define FMA2(d, a, b) asm("fma.rn.f32x2 %0, %1, %2, %0;" : "+l"(d) : "l"(a), "l"(b))

__device__ __forceinline__ unsigned long long dupf(float v) {
    unsigned long long r;
    asm("mov.b64 %0, {%1, %1};" : "=l"(r) : "r"(__float_as_uint(v)));
    return r;
}
__device__ __forceinline__ float lo32(unsigned long long v) {
    return __uint_as_float((unsigned int)(v & 0xffffffffULL));
}
__device__ __forceinline__ float hi32(unsigned long long v) {
    return __uint_as_float((unsigned int)(v >> 32));
}

// ---------------------------------------------------------------------------
// Kernel 0: zero a_sum accumulator
// ---------------------------------------------------------------------------
__global__ void k_zero() {
    int i = blockIdx.x * 256 + threadIdx.x;
    if (i < BB * KK) g_asum[i] = 0.0f;
}

// ---------------------------------------------------------------------------
// Kernel 1: logits GEMM + BN affine + softmax(80) + assignment + a_sum
// Block 256 threads, tile 256 rows x 80 cols. Thread: 8 rows x 10 cols
// (5 f32x2 col-pairs). Cluster cols stored as NATURAL pairs (no dup);
// x broadcast values duplicated in registers (ALU pipe).
// ---------------------------------------------------------------------------
__global__ __launch_bounds__(256) void k_logits(
    const float* __restrict__ x, const float* __restrict__ clusters,
    const float* __restrict__ bnw, const float* __restrict__ bnb,
    const float* __restrict__ rm, const float* __restrict__ rv)
{
    __shared__ __align__(16) float sX[32][258];                 // [d][row], pad for xpose store
    __shared__ __align__(16) unsigned long long sC[32][8][6];   // [d][tx][5 pairs + pad]

    const int tid = threadIdx.x;
    const int tx = tid & 7;        // col group: 10 cols (5 pairs)
    const int ty = tid >> 3;       // row group: 8 rows (0..31)
    const int b = blockIdx.y;
    const int n0 = blockIdx.x * 256;
    const float* xb = x + (size_t)b * NN * DD;

    unsigned long long acc[8][5];
    #pragma unroll
    for (int r = 0; r < 8; r++)
        #pragma unroll
        for (int j = 0; j < 5; j++) acc[r][j] = 0ULL;

    const int dq = tid & 7;        // loader: d-quad
    const int rb = tid >> 3;       // loader: row base

    for (int dt = 0; dt < DD / 32; dt++) {
        // ---- load x tile transposed: sX[d][row] ----
        #pragma unroll
        for (int i = 0; i < 8; i++) {
            int r = rb + i * 32;
            float4 v = *(const float4*)&xb[(size_t)(n0 + r) * DD + dt * 32 + dq * 4];
            sX[dq * 4 + 0][r] = v.x; sX[dq * 4 + 1][r] = v.y;
            sX[dq * 4 + 2][r] = v.z; sX[dq * 4 + 3][r] = v.w;
        }
        // ---- load cluster tile as NATURAL col-pairs ----
        #pragma unroll
        for (int j = 0; j < 5; j++) {
            int idx = tid + j * 256;              // 0..1279
            int d = idx / 40, pc = idx - d * 40;  // pair index 0..39
            float2 cv = *(const float2*)&clusters[(size_t)(dt * 32 + d) * KGC + pc * 2];
            sC[d][pc / 5][pc % 5] = *(const unsigned long long*)&cv;
        }
        __syncthreads();

        #pragma unroll 4
        for (int d = 0; d < 32; d++) {
            // x broadcast: 4x LDS.64, dup in registers
            unsigned long long xd[8];
            #pragma unroll
            for (int p = 0; p < 4; p++) {
                float2 xp = *(const float2*)&sX[d][ty * 8 + 2 * p];
                xd[2 * p]     = dupf(xp.x);
                xd[2 * p + 1] = dupf(xp.y);
            }
            // cluster pairs: 2x LDS.128 + 1x LDS.64
            ulonglong2 c01 = *(const ulonglong2*)&sC[d][tx][0];
            ulonglong2 c23 = *(const ulonglong2*)&sC[d][tx][2];
            unsigned long long Bv[5] = {c01.x, c01.y, c23.x, c23.y, sC[d][tx][4]};
            #pragma unroll
            for (int r = 0; r < 8; r++)
                #pragma unroll
                for (int j = 0; j < 5; j++) FMA2(acc[r][j], xd[r], Bv[j]);
        }
        __syncthreads();
    }

    // BN affine params for my 10 columns
    float scj[10], rmj[10], bbj[10];
    #pragma unroll
    for (int j = 0; j < 10; j++) {
        int c = tx * 10 + j;
        scj[j] = bnw[c] * rsqrtf(rv[c] + 1e-5f);
        rmj[j] = rm[c];
        bbj[j] = bnb[c];
    }

    float colsum[10];
    #pragma unroll
    for (int j = 0; j < 10; j++) colsum[j] = 0.f;

    #pragma unroll
    for (int r = 0; r < 8; r++) {
        float l[10];
        #pragma unroll
        for (int j = 0; j < 5; j++) {
            l[2 * j]     = (lo32(acc[r][j]) - rmj[2 * j]) * scj[2 * j] + bbj[2 * j];
            l[2 * j + 1] = (hi32(acc[r][j]) - rmj[2 * j + 1]) * scj[2 * j + 1] + bbj[2 * j + 1];
        }
        // softmax over 80 cols: 8 threads (tx group) hold one row
        float m = l[0];
        #pragma unroll
        for (int j = 1; j < 10; j++) m = fmaxf(m, l[j]);
        #pragma unroll
        for (int o = 4; o >= 1; o >>= 1) m = fmaxf(m, __shfl_xor_sync(0xffffffffu, m, o));
        float s = 0.f;
        #pragma unroll
        for (int j = 0; j < 10; j++) { l[j] = __expf(l[j] - m); s += l[j]; }
        #pragma unroll
        for (int o = 4; o >= 1; o >>= 1) s += __shfl_xor_sync(0xffffffffu, s, o);
        float inv = 1.0f / s;

        int n = n0 + ty * 8 + r;
        float* arow = &g_assign[((size_t)b * NN + n) * KK];
        #pragma unroll
        for (int j = 0; j < 5; j++) {
            int c = tx * 10 + 2 * j;
            if (c < KK) {
                float a0 = l[2 * j] * inv, a1 = l[2 * j + 1] * inv;
                float2 av = make_float2(a0, a1);
                *(float2*)&arow[c] = av;
                colsum[2 * j] += a0; colsum[2 * j + 1] += a1;
            }
        }
    }

    // reduce colsum over 32 ty groups -> a_sum (reuse sC memory)
    float (*sRed)[80] = (float(*)[80])sC;
    #pragma unroll
    for (int j = 0; j < 10; j++) sRed[ty][tx * 10 + j] = colsum[j];
    __syncthreads();
    if (tid < KK) {
        float s = 0.f;
        #pragma unroll
        for (int t = 0; t < 32; t++) s += sRed[t][tid];
        atomicAdd(&g_asum[b * KK + tid], s);
    }
}

// ---------------------------------------------------------------------------
// Kernel 2: partial vlad[b,d,k] += sum_{n in chunk} x[b,n,d]*assign[b,n,k]
// Block 256 threads, tile 128 d x 64 k, n-chunk 512. Grid (4 dtiles, 4 chunks, B).
// Thread: 4 d x 8 k (4 f32x2 k-pairs). Assignment stored as natural pairs.
// ---------------------------------------------------------------------------
__global__ __launch_bounds__(256) void k_vlad(const float* __restrict__ x)
{
    __shared__ __align__(16) float sXv[32][128];              // [n][d]
    __shared__ __align__(16) unsigned long long sA[32][32];   // [n][k-pair]

    const int tid = threadIdx.x;
    const int tx = tid & 7;       // k-pair group (4 pairs = 8 k)
    const int ty = tid >> 3;      // d group (4 d each), 0..31
    const int b = blockIdx.z;
    const int chunk = blockIdx.y;
    const int d0 = blockIdx.x * 128;
    const float* xb = x + (size_t)b * NN * DD;
    const float* ab = g_assign + (size_t)b * NN * KK;

    unsigned long long acc[4][4];
    #pragma unroll
    for (int p = 0; p < 4; p++)
        #pragma unroll
        for (int q = 0; q < 4; q++) acc[p][q] = 0ULL;

    for (int nt = 0; nt < 16; nt++) {
        const int nbase = chunk * 512 + nt * 32;
        // x tile [32 n][128 d], natural layout, float4 coalesced
        #pragma unroll
        for (int j = 0; j < 4; j++) {
            int idx = tid + j * 256;          // 0..1023 float4s
            int n = idx >> 5, dq = idx & 31;
            float4 v = *(const float4*)&xb[(size_t)(nbase + n) * DD + d0 + dq * 4];
            *(float4*)&sXv[n][dq * 4] = v;
        }
        // assignment tile as natural k-pairs
        #pragma unroll
        for (int j = 0; j < 2; j++) {
            int idx = tid + j * 256;          // 0..511 float4s
            int n = idx >> 4, q4 = idx & 15;
            float4 v = *(const float4*)&ab[(size_t)(nbase + n) * KK + q4 * 4];
            *(ulonglong2*)&sA[n][q4 * 2] = *(const ulonglong2*)&v;
        }
        __syncthreads();

        #pragma unroll 4
        for (int n = 0; n < 32; n++) {
            unsigned long long xd[4];
            #pragma unroll
            for (int p = 0; p < 2; p++) {
                float2 xp = *(const float2*)&sXv[n][ty * 4 + 2 * p];
                xd[2 * p]     = dupf(xp.x);
                xd[2 * p + 1] = dupf(xp.y);
            }
            ulonglong2 a01 = *(const ulonglong2*)&sA[n][tx * 4];
            ulonglong2 a23 = *(const ulonglong2*)&sA[n][tx * 4 + 2];
            unsigned long long Av[4] = {a01.x, a01.y, a23.x, a23.y};
            #pragma unroll
            for (int p = 0; p < 4; p++)
                #pragma unroll
                for (int q = 0; q < 4; q++) FMA2(acc[p][q], xd[p], Av[q]);
        }
        __syncthreads();
    }

    // stream partials (no atomics)
    float* vp = g_vpart[chunk] + ((size_t)b * DD + d0) * KK;
    #pragma unroll
    for (int p = 0; p < 4; p++) {
        int d = ty * 4 + p;
        #pragma unroll
        for (int q = 0; q < 4; q++)
            *(unsigned long long*)&vp[(size_t)d * KK + tx * 8 + q * 2] = acc[p][q];
    }
}

// ---------------------------------------------------------------------------
// Kernel 3: finisher — sum 4 partials, subtract a_sum*clusters2, write vlad,
// compute per-(b,k) norm^2 (one block per b, no atomics).
// ---------------------------------------------------------------------------
__global__ __launch_bounds__(256) void k_fin(const float* __restrict__ clusters2)
{
    __shared__ float sN[4][KK];
    const int b = blockIdx.x;
    const int k = threadIdx.x & 63;
    const int dg = threadIdx.x >> 6;   // 0..3
    const float as = g_asum[b * KK + k];

    float n2 = 0.f;
    for (int i = 0; i < 128; i++) {
        int d = dg * 128 + i;
        size_t off = ((size_t)b * DD + d) * KK + k;
        float v = g_vpart[0][off] + g_vpart[1][off] + g_vpart[2][off] + g_vpart[3][off];
        v -= as * clusters2[(size_t)d * KK + k];
        g_vlad[off] = v;
        n2 += v * v;
    }
    sN[dg][k] = n2;
    __syncthreads();
    if (threadIdx.x < KK)
        g_norm2[b * KK + k] = sN[0][k] + sN[1][k] + sN[2][k] + sN[3][k];
}

// ---------------------------------------------------------------------------
// Kernel 4: per-(b,k) combined scale
// ---------------------------------------------------------------------------
__global__ void k_colscale() {
    int b = blockIdx.x;
    int k = threadIdx.x;   // 64 threads
    float n2 = g_norm2[b * KK + k];
    float nr = sqrtf(n2);
    float inv = 1.0f / fmaxf(nr, 1e-12f);
    float c = n2 * inv * inv;
    __shared__ float sh[2];
    #pragma unroll
    for (int o = 16; o >= 1; o >>= 1) c += __shfl_xor_sync(0xffffffffu, c, o);
    if ((threadIdx.x & 31) == 0) sh[threadIdx.x >> 5] = c;
    __syncthreads();
    float tot = sqrtf(sh[0] + sh[1]);
    float invt = 1.0f / fmaxf(tot, 1e-12f);
    g_scale[b * KK + k] = inv * invt;
}

// ---------------------------------------------------------------------------
// Kernel 5: out[b, d*K+k] = vlad[b,d,k] * scale[b,k]
// ---------------------------------------------------------------------------
__global__ void k_out(float* __restrict__ out) {
    int i = blockIdx.x * 256 + threadIdx.x;
    int b = i >> 15;
    int k = i & 63;
    out[i] = g_vlad[i] * g_scale[(b << 6) + k];
}

// ---------------------------------------------------------------------------
extern "C" void kernel_launch(void* const* d_in, const int* in_sizes, int n_in,
                              void* d_out, int out_size) {
    const float* x         = (const float*)d_in[0];
    const float* clusters  = (const float*)d_in[1];
    const float* clusters2 = (const float*)d_in[2];
    const float* bnw       = (const float*)d_in[3];
    const float* bnb       = (const float*)d_in[4];
    const float* rm        = (const float*)d_in[5];
    const float* rv        = (const float*)d_in[6];
    float* out = (float*)d_out;

    k_zero<<<(BB * KK + 255) / 256, 256>>>();
    dim3 g1(NN / 256, BB);
    k_logits<<<g1, 256>>>(x, clusters, bnw, bnb, rm, rv);
    dim3 g2(DD / 128, 4, BB);
    k_vlad<<<g2, 256>>>(x);
    k_fin<<<BB, 256>>>(clusters2);
    k_colscale<<<BB, KK>>>();
    k_out<<<(BB * DD * KK) / 256, 256>>>(out);
}

// round 3
// speedup vs baseline: 2.0623x; 1.5458x over previous
#include <cuda_runtime.h>

#define BB 64
#define NN 2048
#define DD 512
#define KK 64
#define KGC 80

// Scratch (device globals — no allocation allowed)
__device__ float g_assign[BB * NN * KK];          // 32 MB
__device__ float g_vpart[2][BB * DD * KK];        // 16 MB (per-n-chunk partials)
__device__ float g_asum[BB * KK];
__device__ float g_norm2[BB * KK];
__device__ float g_scale[BB * KK];

// Packed fp32x2 FMA (SASS FFMA2) — 2x fp32 throughput, exact fp32 rounding
#define FMA2(d, a, b) asm("fma.rn.f32x2 %0, %1, %2, %0;" : "+l"(d) : "l"(a), "l"(b))

__device__ __forceinline__ unsigned long long dupf(float v) {
    unsigned long long r;
    asm("mov.b64 %0, {%1, %1};" : "=l"(r) : "r"(__float_as_uint(v)));
    return r;
}
__device__ __forceinline__ float lo32(unsigned long long v) {
    return __uint_as_float((unsigned int)(v & 0xffffffffULL));
}
__device__ __forceinline__ float hi32(unsigned long long v) {
    return __uint_as_float((unsigned int)(v >> 32));
}

// ---------------------------------------------------------------------------
// Kernel 0: zero accumulators
// ---------------------------------------------------------------------------
__global__ void k_zero() {
    int i = blockIdx.x * 256 + threadIdx.x;
    if (i < BB * KK) { g_asum[i] = 0.0f; g_norm2[i] = 0.0f; }
}

// ---------------------------------------------------------------------------
// Kernel 1: logits GEMM + BN affine + softmax(80) + assignment + a_sum
// Block 128 threads (3 blocks/SM), tile 128 rows x 80 cols.
// Thread: 8 rows x 10 cols (5 f32x2 col-pairs).
// ---------------------------------------------------------------------------
__global__ __launch_bounds__(128, 3) void k_logits(
    const float* __restrict__ x, const float* __restrict__ clusters,
    const float* __restrict__ bnw, const float* __restrict__ bnb,
    const float* __restrict__ rm, const float* __restrict__ rv)
{
    __shared__ __align__(16) float sX[32][132];                 // [d][row]
    __shared__ __align__(16) unsigned long long sC[32][8][6];   // [d][tx][5 pairs + pad]

    const int tid = threadIdx.x;
    const int tx = tid & 7;        // col group: 10 cols (5 pairs)
    const int ty = tid >> 3;       // row group: 8 rows (0..15)
    const int b = blockIdx.y;
    const int n0 = blockIdx.x * 128;
    const float* xb = x + (size_t)b * NN * DD;

    unsigned long long acc[8][5];
    #pragma unroll
    for (int r = 0; r < 8; r++)
        #pragma unroll
        for (int j = 0; j < 5; j++) acc[r][j] = 0ULL;

    const int dq = tid & 7;        // loader: d-quad
    const int rb = tid >> 3;       // loader: row base (0..15)

    for (int dt = 0; dt < DD / 32; dt++) {
        // ---- load x tile transposed: sX[d][row] ----
        #pragma unroll
        for (int i = 0; i < 8; i++) {
            int r = rb + i * 16;
            float4 v = *(const float4*)&xb[(size_t)(n0 + r) * DD + dt * 32 + dq * 4];
            sX[dq * 4 + 0][r] = v.x; sX[dq * 4 + 1][r] = v.y;
            sX[dq * 4 + 2][r] = v.z; sX[dq * 4 + 3][r] = v.w;
        }
        // ---- load cluster tile as NATURAL col-pairs ----
        #pragma unroll
        for (int j = 0; j < 10; j++) {
            int idx = tid + j * 128;              // 0..1279
            int d = idx / 40, pc = idx - d * 40;  // pair index 0..39
            float2 cv = *(const float2*)&clusters[(size_t)(dt * 32 + d) * KGC + pc * 2];
            sC[d][pc / 5][pc % 5] = *(const unsigned long long*)&cv;
        }
        __syncthreads();

        #pragma unroll 4
        for (int d = 0; d < 32; d++) {
            unsigned long long xd[8];
            #pragma unroll
            for (int p = 0; p < 4; p++) {
                float2 xp = *(const float2*)&sX[d][ty * 8 + 2 * p];
                xd[2 * p]     = dupf(xp.x);
                xd[2 * p + 1] = dupf(xp.y);
            }
            ulonglong2 c01 = *(const ulonglong2*)&sC[d][tx][0];
            ulonglong2 c23 = *(const ulonglong2*)&sC[d][tx][2];
            unsigned long long Bv[5] = {c01.x, c01.y, c23.x, c23.y, sC[d][tx][4]};
            #pragma unroll
            for (int r = 0; r < 8; r++)
                #pragma unroll
                for (int j = 0; j < 5; j++) FMA2(acc[r][j], xd[r], Bv[j]);
        }
        __syncthreads();
    }

    // BN affine params for my 10 columns
    float scj[10], rmj[10], bbj[10];
    #pragma unroll
    for (int j = 0; j < 10; j++) {
        int c = tx * 10 + j;
        scj[j] = bnw[c] * rsqrtf(rv[c] + 1e-5f);
        rmj[j] = rm[c];
        bbj[j] = bnb[c];
    }

    float colsum[10];
    #pragma unroll
    for (int j = 0; j < 10; j++) colsum[j] = 0.f;

    #pragma unroll
    for (int r = 0; r < 8; r++) {
        float l[10];
        #pragma unroll
        for (int j = 0; j < 5; j++) {
            l[2 * j]     = (lo32(acc[r][j]) - rmj[2 * j]) * scj[2 * j] + bbj[2 * j];
            l[2 * j + 1] = (hi32(acc[r][j]) - rmj[2 * j + 1]) * scj[2 * j + 1] + bbj[2 * j + 1];
        }
        // softmax over 80 cols: 8 threads (same ty) hold one row
        float m = l[0];
        #pragma unroll
        for (int j = 1; j < 10; j++) m = fmaxf(m, l[j]);
        #pragma unroll
        for (int o = 4; o >= 1; o >>= 1) m = fmaxf(m, __shfl_xor_sync(0xffffffffu, m, o));
        float s = 0.f;
        #pragma unroll
        for (int j = 0; j < 10; j++) { l[j] = __expf(l[j] - m); s += l[j]; }
        #pragma unroll
        for (int o = 4; o >= 1; o >>= 1) s += __shfl_xor_sync(0xffffffffu, s, o);
        float inv = 1.0f / s;

        int n = n0 + ty * 8 + r;
        float* arow = &g_assign[((size_t)b * NN + n) * KK];
        #pragma unroll
        for (int j = 0; j < 5; j++) {
            int c = tx * 10 + 2 * j;
            if (c < KK) {
                float a0 = l[2 * j] * inv, a1 = l[2 * j + 1] * inv;
                float2 av = make_float2(a0, a1);
                *(float2*)&arow[c] = av;
                colsum[2 * j] += a0; colsum[2 * j + 1] += a1;
            }
        }
    }

    // reduce colsum over 16 ty groups -> a_sum (reuse sC memory)
    float (*sRed)[80] = (float(*)[80])sC;
    #pragma unroll
    for (int j = 0; j < 10; j++) sRed[ty][tx * 10 + j] = colsum[j];
    __syncthreads();
    if (tid < KK) {
        float s = 0.f;
        #pragma unroll
        for (int t = 0; t < 16; t++) s += sRed[t][tid];
        atomicAdd(&g_asum[b * KK + tid], s);
    }
}

// ---------------------------------------------------------------------------
// Kernel 2: partial vlad[b,d,k] += sum_{n in chunk} x[b,n,d]*assign[b,n,k]
// Block 128 threads (4 blocks/SM), tile 128 d x 64 k, n-chunk 1024.
// Grid (4 dtiles, 2 chunks, B) = 512 blocks (one full resident wave).
// Thread: 8 d x 8 k (4 f32x2 k-pairs).
// ---------------------------------------------------------------------------
__global__ __launch_bounds__(128, 4) void k_vlad(const float* __restrict__ x)
{
    __shared__ __align__(16) float sXv[32][128];              // [n][d]
    __shared__ __align__(16) unsigned long long sA[32][32];   // [n][k-pair]

    const int tid = threadIdx.x;
    const int tx = tid & 7;       // k-pair group (4 pairs = 8 k)
    const int ty = tid >> 3;      // d group (8 d each), 0..15
    const int b = blockIdx.z;
    const int chunk = blockIdx.y;
    const int d0 = blockIdx.x * 128;
    const float* xb = x + (size_t)b * NN * DD;
    const float* ab = g_assign + (size_t)b * NN * KK;

    unsigned long long acc[8][4];
    #pragma unroll
    for (int p = 0; p < 8; p++)
        #pragma unroll
        for (int q = 0; q < 4; q++) acc[p][q] = 0ULL;

    for (int nt = 0; nt < 32; nt++) {
        const int nbase = chunk * 1024 + nt * 32;
        // x tile [32 n][128 d]
        #pragma unroll
        for (int j = 0; j < 8; j++) {
            int idx = tid + j * 128;          // 0..1023 float4s
            int n = idx >> 5, dq = idx & 31;
            float4 v = *(const float4*)&xb[(size_t)(nbase + n) * DD + d0 + dq * 4];
            *(float4*)&sXv[n][dq * 4] = v;
        }
        // assignment tile as natural k-pairs
        #pragma unroll
        for (int j = 0; j < 4; j++) {
            int idx = tid + j * 128;          // 0..511 float4s
            int n = idx >> 4, q4 = idx & 15;
            float4 v = *(const float4*)&ab[(size_t)(nbase + n) * KK + q4 * 4];
            *(ulonglong2*)&sA[n][q4 * 2] = *(const ulonglong2*)&v;
        }
        __syncthreads();

        #pragma unroll 4
        for (int n = 0; n < 32; n++) {
            unsigned long long xd[8];
            #pragma unroll
            for (int p = 0; p < 4; p++) {
                float2 xp = *(const float2*)&sXv[n][ty * 8 + 2 * p];
                xd[2 * p]     = dupf(xp.x);
                xd[2 * p + 1] = dupf(xp.y);
            }
            ulonglong2 a01 = *(const ulonglong2*)&sA[n][tx * 4];
            ulonglong2 a23 = *(const ulonglong2*)&sA[n][tx * 4 + 2];
            unsigned long long Av[4] = {a01.x, a01.y, a23.x, a23.y};
            #pragma unroll
            for (int p = 0; p < 8; p++)
                #pragma unroll
                for (int q = 0; q < 4; q++) FMA2(acc[p][q], xd[p], Av[q]);
        }
        __syncthreads();
    }

    // stream partials (no atomics)
    float* vp = g_vpart[chunk] + ((size_t)b * DD + d0) * KK;
    #pragma unroll
    for (int p = 0; p < 8; p++) {
        int d = ty * 8 + p;
        ulonglong2 v0; v0.x = acc[p][0]; v0.y = acc[p][1];
        ulonglong2 v1; v1.x = acc[p][2]; v1.y = acc[p][3];
        *(ulonglong2*)&vp[(size_t)d * KK + tx * 8]     = v0;
        *(ulonglong2*)&vp[(size_t)d * KK + tx * 8 + 4] = v1;
    }
}

// ---------------------------------------------------------------------------
// Kernel 3: finisher — sum 2 partials, subtract a_sum*clusters2, write vlad
// straight into d_out, accumulate per-(b,k) norm^2. Grid (8 dgroups, B).
// ---------------------------------------------------------------------------
__global__ __launch_bounds__(256) void k_fin(const float* __restrict__ clusters2,
                                             float* __restrict__ out)
{
    __shared__ float sN[4][KK];
    const int b = blockIdx.y;
    const int dg = blockIdx.x;          // 0..7, 64 d each
    const int k = threadIdx.x & 63;
    const int ds = threadIdx.x >> 6;    // 0..3, 16 d each
    const float as = g_asum[b * KK + k];

    float n2 = 0.f;
    #pragma unroll 4
    for (int i = 0; i < 16; i++) {
        int d = dg * 64 + ds * 16 + i;
        size_t off = ((size_t)b * DD + d) * KK + k;
        float v = g_vpart[0][off] + g_vpart[1][off];
        v -= as * clusters2[(size_t)d * KK + k];
        out[off] = v;
        n2 += v * v;
    }
    sN[ds][k] = n2;
    __syncthreads();
    if (threadIdx.x < KK)
        atomicAdd(&g_norm2[b * KK + k], sN[0][k] + sN[1][k] + sN[2][k] + sN[3][k]);
}

// ---------------------------------------------------------------------------
// Kernel 4: per-(b,k) combined scale
// ---------------------------------------------------------------------------
__global__ void k_colscale() {
    int b = blockIdx.x;
    int k = threadIdx.x;   // 64 threads
    float n2 = g_norm2[b * KK + k];
    float nr = sqrtf(n2);
    float inv = 1.0f / fmaxf(nr, 1e-12f);
    float c = n2 * inv * inv;
    __shared__ float sh[2];
    #pragma unroll
    for (int o = 16; o >= 1; o >>= 1) c += __shfl_xor_sync(0xffffffffu, c, o);
    if ((threadIdx.x & 31) == 0) sh[threadIdx.x >> 5] = c;
    __syncthreads();
    float tot = sqrtf(sh[0] + sh[1]);
    float invt = 1.0f / fmaxf(tot, 1e-12f);
    g_scale[b * KK + k] = inv * invt;
}

// ---------------------------------------------------------------------------
// Kernel 5: in-place scale of d_out
// ---------------------------------------------------------------------------
__global__ void k_out(float* __restrict__ out) {
    int i = blockIdx.x * 256 + threadIdx.x;
    int b = i >> 15;
    int k = i & 63;
    out[i] = out[i] * g_scale[(b << 6) + k];
}

// ---------------------------------------------------------------------------
extern "C" void kernel_launch(void* const* d_in, const int* in_sizes, int n_in,
                              void* d_out, int out_size) {
    const float* x         = (const float*)d_in[0];
    const float* clusters  = (const float*)d_in[1];
    const float* clusters2 = (const float*)d_in[2];
    const float* bnw       = (const float*)d_in[3];
    const float* bnb       = (const float*)d_in[4];
    const float* rm        = (const float*)d_in[5];
    const float* rv        = (const float*)d_in[6];
    float* out = (float*)d_out;

    k_zero<<<(BB * KK + 255) / 256, 256>>>();
    dim3 g1(NN / 128, BB);
    k_logits<<<g1, 128>>>(x, clusters, bnw, bnb, rm, rv);
    dim3 g2(DD / 128, 2, BB);
    k_vlad<<<g2, 128>>>(x);
    dim3 g3(8, BB);
    k_fin<<<g3, 256>>>(clusters2, out);
    k_colscale<<<BB, KK>>>();
    k_out<<<(BB * DD * KK) / 256, 256>>>(out);
}

// round 5
// speedup vs baseline: 2.6451x; 1.2826x over previous
#include <cuda_runtime.h>
#include <cuda_bf16.h>
#include <cstdint>

#define BB 64
#define NN 2048
#define DD 512
#define KK 64
#define KGC 80

// Scratch (device globals — no allocation allowed)
__device__ __nv_bfloat16 g_aThi[(size_t)BB * KK * NN];   // assignment^T hi [b][k][n]
__device__ __nv_bfloat16 g_aTlo[(size_t)BB * KK * NN];   // assignment^T lo
__device__ float g_vpart[(size_t)BB * KK * DD];          // vlad sums [b][k][d]
__device__ float g_asum[BB * KK];
__device__ float g_norm2[BB * KK];
__device__ float g_scale[BB * KK];
__device__ __nv_bfloat16 g_cHi[DD * KGC];                // clusters hi split [d][c]
__device__ __nv_bfloat16 g_cLo[DD * KGC];                // clusters lo split
__device__ float g_c2T[KK * DD];                         // clusters2^T [k][d]

// ===================== mma.sync / ldmatrix helpers (sm_80+, no 'a' features) ==
__device__ __forceinline__ uint32_t smem_to_u32(const void* p) {
    uint32_t a;
    asm("{ .reg .u64 t; cvta.to.shared.u64 t, %1; cvt.u32.u64 %0, t; }" : "=r"(a) : "l"(p));
    return a;
}
__device__ __forceinline__ void mma_bf16(float* c, const uint32_t* a, const uint32_t* b) {
    asm volatile("mma.sync.aligned.m16n8k16.row.col.f32.bf16.bf16.f32 "
        "{%0,%1,%2,%3}, {%4,%5,%6,%7}, {%8,%9}, {%0,%1,%2,%3};"
        : "+f"(c[0]), "+f"(c[1]), "+f"(c[2]), "+f"(c[3])
        : "r"(a[0]), "r"(a[1]), "r"(a[2]), "r"(a[3]), "r"(b[0]), "r"(b[1]));
}
__device__ __forceinline__ void ldsm_x4(uint32_t* r, uint32_t addr) {
    asm volatile("ldmatrix.sync.aligned.m8n8.x4.shared.b16 {%0,%1,%2,%3}, [%4];"
        : "=r"(r[0]), "=r"(r[1]), "=r"(r[2]), "=r"(r[3]) : "r"(addr));
}
__device__ __forceinline__ void ldsm_x2t(uint32_t* r, uint32_t addr) {
    asm volatile("ldmatrix.sync.aligned.m8n8.x2.trans.shared.b16 {%0,%1}, [%2];"
        : "=r"(r[0]), "=r"(r[1]) : "r"(addr));
}
__device__ __forceinline__ void split2(float2 v, uint32_t& hi, uint32_t& lo) {
    __nv_bfloat162 h = __float22bfloat162_rn(v);
    float2 hf = __bfloat1622float2(h);
    __nv_bfloat162 l = __float22bfloat162_rn(make_float2(v.x - hf.x, v.y - hf.y));
    hi = *(uint32_t*)&h;
    lo = *(uint32_t*)&l;
}

// ---------------------------------------------------------------------------
// Kernel 0: zero accumulators
// ---------------------------------------------------------------------------
__global__ void k_zero() {
    int i = blockIdx.x * 256 + threadIdx.x;
    if (i < BB * KK) { g_asum[i] = 0.0f; g_norm2[i] = 0.0f; }
}

// ---------------------------------------------------------------------------
// Kernel P1: split clusters [512][80] into bf16 hi/lo (layout unchanged: K-major)
// ---------------------------------------------------------------------------
__global__ void k_prep(const float* __restrict__ clusters) {
    int i = blockIdx.x * 256 + threadIdx.x;
    if (i < DD * KGC) {
        float v = clusters[i];
        __nv_bfloat16 h = __float2bfloat16(v);
        g_cHi[i] = h;
        g_cLo[i] = __float2bfloat16(v - __bfloat162float(h));
    }
}
// Kernel P2: transpose clusters2 [512][64] -> [64][512]
__global__ void k_prep2(const float* __restrict__ clusters2) {
    int k = blockIdx.x;
    int d = threadIdx.x;
    g_c2T[k * DD + d] = clusters2[d * KK + k];
}

// ---------------------------------------------------------------------------
// Kernel 1: logits GEMM (mma.sync bf16x3) + BN + softmax + a_sum + assignT
// CTA: 128 threads (4 warps, M-split), tile M=128 n-rows x N=80 cols, K=512
// in 8 chunks of 64 staged in smem (fp32->bf16 hi/lo conversion during load).
// ---------------------------------------------------------------------------
#define L_SAH 0          // x hi:   [128][72] bf16, 144B stride -> 18432B
#define L_SAL 18432      // x lo
#define L_SBH 36864      // c hi:   [64][88] bf16, 176B stride -> 11264B
#define L_SBL 48128      // c lo
#define L_BN  59392      // 240 floats
#define L_AS  60352      // 128 floats
#define L_SMEM 60928

__global__ __launch_bounds__(128) void k_logits_mma(
    const float* __restrict__ x,
    const float* __restrict__ bnw, const float* __restrict__ bnb,
    const float* __restrict__ rm, const float* __restrict__ rv)
{
    extern __shared__ __align__(16) char smem[];
    const int tid = threadIdx.x;
    const int lane = tid & 31, w = tid >> 5;
    const int b = blockIdx.y, n0 = blockIdx.x * 128;
    const float* xb = x + ((size_t)b * NN + n0) * DD;
    uint32_t sb32 = smem_to_u32(smem);

    float* sScale = (float*)(smem + L_BN);
    float* sRm = sScale + 80;
    float* sBb = sScale + 160;
    if (tid < KGC) {
        sScale[tid] = bnw[tid] * rsqrtf(rv[tid] + 1e-5f);
        sRm[tid] = rm[tid];
        sBb[tid] = bnb[tid];
    }

    float acc[2][10][4];
    #pragma unroll
    for (int mt = 0; mt < 2; mt++)
        #pragma unroll
        for (int nt = 0; nt < 10; nt++)
            #pragma unroll
            for (int e = 0; e < 4; e++) acc[mt][nt][e] = 0.f;

    const int arow = w * 32 + (lane & 15);       // ldmatrix A row
    const int acol = (lane >> 4) * 8;            // ldmatrix A col offset (bf16)
    const int brow = lane & 15;                  // ldmatrix B row

    for (int dt = 0; dt < 8; dt++) {
        // ---- stage x chunk [128 n][64 d] fp32 -> bf16 hi/lo ----
        #pragma unroll
        for (int j = 0; j < 16; j++) {
            int fidx = tid + j * 128;
            int r = fidx >> 4, u = fidx & 15;
            float4 v = *(const float4*)&xb[(size_t)r * DD + dt * 64 + u * 4];
            uint32_t h0, l0, h1, l1;
            split2(make_float2(v.x, v.y), h0, l0);
            split2(make_float2(v.z, v.w), h1, l1);
            int off = r * 144 + u * 8;
            *(uint2*)(smem + L_SAH + off) = make_uint2(h0, h1);
            *(uint2*)(smem + L_SAL + off) = make_uint2(l0, l1);
        }
        // ---- stage clusters chunk [64 d][80 c] bf16 ----
        #pragma unroll
        for (int j = 0; j < 5; j++) {
            int idx = tid + j * 128;              // 0..639 16B units
            int r = idx / 10, u = idx - r * 10;
            size_t ge = (size_t)(dt * 64 + r) * KGC + u * 8;
            uint4 vh = *(const uint4*)(g_cHi + ge);
            uint4 vl = *(const uint4*)(g_cLo + ge);
            int off = r * 176 + u * 16;
            *(uint4*)(smem + L_SBH + off) = vh;
            *(uint4*)(smem + L_SBL + off) = vl;
        }
        __syncthreads();

        #pragma unroll
        for (int kt = 0; kt < 4; kt++) {
            uint32_t ah[2][4], al[2][4];
            #pragma unroll
            for (int mt = 0; mt < 2; mt++) {
                uint32_t aoff = (uint32_t)((arow + mt * 16) * 144 + (kt * 16 + acol) * 2);
                ldsm_x4(ah[mt], sb32 + L_SAH + aoff);
                ldsm_x4(al[mt], sb32 + L_SAL + aoff);
            }
            #pragma unroll
            for (int nt = 0; nt < 10; nt++) {
                uint32_t boff = (uint32_t)((kt * 16 + brow) * 176 + nt * 16);
                uint32_t bh[2], bl[2];
                ldsm_x2t(bh, sb32 + L_SBH + boff);
                ldsm_x2t(bl, sb32 + L_SBL + boff);
                #pragma unroll
                for (int mt = 0; mt < 2; mt++) {
                    mma_bf16(acc[mt][nt], ah[mt], bh);
                    mma_bf16(acc[mt][nt], ah[mt], bl);
                    mma_bf16(acc[mt][nt], al[mt], bh);
                }
            }
        }
        __syncthreads();
    }

    // ---- BN affine (col = nt*8 + (lane&3)*2 + e) ----
    #pragma unroll
    for (int nt = 0; nt < 10; nt++) {
        int c0 = nt * 8 + (lane & 3) * 2;
        float s0 = sScale[c0], s1 = sScale[c0 + 1];
        float m0 = sRm[c0],    m1 = sRm[c0 + 1];
        float q0 = sBb[c0],    q1 = sBb[c0 + 1];
        #pragma unroll
        for (int mt = 0; mt < 2; mt++) {
            acc[mt][nt][0] = (acc[mt][nt][0] - m0) * s0 + q0;
            acc[mt][nt][1] = (acc[mt][nt][1] - m1) * s1 + q1;
            acc[mt][nt][2] = (acc[mt][nt][2] - m0) * s0 + q0;
            acc[mt][nt][3] = (acc[mt][nt][3] - m1) * s1 + q1;
        }
    }

    // ---- softmax per row (4 lanes of a quad hold 20 cols each) ----
    float* sOut = (float*)smem;                  // reuse A region: [128][66] floats
    #pragma unroll
    for (int mt = 0; mt < 2; mt++) {
        #pragma unroll
        for (int h = 0; h < 2; h++) {
            float mx = -3.4e38f;
            #pragma unroll
            for (int nt = 0; nt < 10; nt++)
                mx = fmaxf(mx, fmaxf(acc[mt][nt][h * 2], acc[mt][nt][h * 2 + 1]));
            mx = fmaxf(mx, __shfl_xor_sync(0xffffffffu, mx, 1));
            mx = fmaxf(mx, __shfl_xor_sync(0xffffffffu, mx, 2));
            float e[10][2];
            float sum = 0.f;
            #pragma unroll
            for (int nt = 0; nt < 10; nt++) {
                e[nt][0] = __expf(acc[mt][nt][h * 2] - mx);
                e[nt][1] = __expf(acc[mt][nt][h * 2 + 1] - mx);
                sum += e[nt][0] + e[nt][1];
            }
            sum += __shfl_xor_sync(0xffffffffu, sum, 1);
            sum += __shfl_xor_sync(0xffffffffu, sum, 2);
            float inv = 1.0f / sum;
            int row = w * 32 + mt * 16 + h * 8 + (lane >> 2);
            #pragma unroll
            for (int nt = 0; nt < 8; nt++) {     // only first 64 cols kept
                float2 v = make_float2(e[nt][0] * inv, e[nt][1] * inv);
                *(float2*)&sOut[row * 66 + nt * 8 + (lane & 3) * 2] = v;
            }
        }
    }
    __syncthreads();

    // ---- a_sum ----
    float* sAs = (float*)(smem + L_AS);
    {
        int k = tid & 63, half = tid >> 6;
        float s = 0.f;
        #pragma unroll 8
        for (int r = half * 64; r < half * 64 + 64; r++) s += sOut[r * 66 + k];
        sAs[half * 64 + k] = s;
    }
    __syncthreads();
    if (tid < KK) atomicAdd(&g_asum[b * KK + tid], sAs[tid] + sAs[64 + tid]);

    // ---- assignment^T as bf16 hi/lo: g_aT*[b][k][n0+tid] ----
    __nv_bfloat16* aThi = g_aThi + (size_t)b * KK * NN + n0 + tid;
    __nv_bfloat16* aTlo = g_aTlo + (size_t)b * KK * NN + n0 + tid;
    #pragma unroll 4
    for (int k = 0; k < KK; k++) {
        float v = sOut[tid * 66 + k];
        __nv_bfloat16 h = __float2bfloat16(v);
        aThi[(size_t)k * NN] = h;
        aTlo[(size_t)k * NN] = __float2bfloat16(v - __bfloat162float(h));
    }
}

// ---------------------------------------------------------------------------
// Kernel 2: vlad GEMM (mma.sync bf16x3): D[k_clu][d] = assign^T @ x
// CTA: 128 threads (4 warps, N(d)-split), tile M=64 k_clu x N=128 d, K=n=2048
// in 64 chunks of 32. Writes full sums to g_vpart[b][k][d].
// ---------------------------------------------------------------------------
#define V_BXH 0          // x hi: [32][136] bf16, 272B stride -> 8704B
#define V_BXL 8704
#define V_ATH 17408      // aT hi: [64][40] bf16, 80B stride -> 5120B
#define V_ATL 22528      // -> 27648B total

__global__ __launch_bounds__(128) void k_vlad_mma(const float* __restrict__ x)
{
    __shared__ __align__(16) char sm[27648];
    const int tid = threadIdx.x, lane = tid & 31, w = tid >> 5;
    const int b = blockIdx.y, d0 = blockIdx.x * 128;
    const float* xb = x + (size_t)b * NN * DD + d0;
    const __nv_bfloat16* aThi = g_aThi + (size_t)b * KK * NN;
    const __nv_bfloat16* aTlo = g_aTlo + (size_t)b * KK * NN;
    uint32_t sb32 = smem_to_u32(sm);

    float acc[4][4][4];
    #pragma unroll
    for (int mt = 0; mt < 4; mt++)
        #pragma unroll
        for (int nt = 0; nt < 4; nt++)
            #pragma unroll
            for (int e = 0; e < 4; e++) acc[mt][nt][e] = 0.f;

    for (int nc = 0; nc < NN / 32; nc++) {
        const int nbase = nc * 32;
        // x tile [32 n][128 d] fp32 -> bf16 hi/lo
        #pragma unroll
        for (int j = 0; j < 8; j++) {
            int idx = tid + j * 128;
            int r = idx >> 5, u = idx & 31;
            float4 v = *(const float4*)&xb[(size_t)(nbase + r) * DD + u * 4];
            uint32_t h0, l0, h1, l1;
            split2(make_float2(v.x, v.y), h0, l0);
            split2(make_float2(v.z, v.w), h1, l1);
            int off = r * 272 + u * 8;
            *(uint2*)(sm + V_BXH + off) = make_uint2(h0, h1);
            *(uint2*)(sm + V_BXL + off) = make_uint2(l0, l1);
        }
        // aT tile [64 k][32 n] bf16 hi/lo
        #pragma unroll
        for (int j = 0; j < 2; j++) {
            int idx = tid + j * 128;              // 0..255 16B units
            int r = idx >> 2, u = idx & 3;
            size_t ge = (size_t)r * NN + nbase + u * 8;
            uint4 vh = *(const uint4*)(aThi + ge);
            uint4 vl = *(const uint4*)(aTlo + ge);
            int off = r * 80 + u * 16;
            *(uint4*)(sm + V_ATH + off) = vh;
            *(uint4*)(sm + V_ATL + off) = vl;
        }
        __syncthreads();

        #pragma unroll
        for (int kt = 0; kt < 2; kt++) {
            uint32_t ah[4][4], al[4][4];
            #pragma unroll
            for (int mt = 0; mt < 4; mt++) {
                uint32_t aoff = (uint32_t)((mt * 16 + (lane & 15)) * 80 +
                                           (kt * 16 + (lane >> 4) * 8) * 2);
                ldsm_x4(ah[mt], sb32 + V_ATH + aoff);
                ldsm_x4(al[mt], sb32 + V_ATL + aoff);
            }
            #pragma unroll
            for (int nt = 0; nt < 4; nt++) {
                uint32_t boff = (uint32_t)((kt * 16 + (lane & 15)) * 272 +
                                           (w * 32 + nt * 8) * 2);
                uint32_t bh[2], bl[2];
                ldsm_x2t(bh, sb32 + V_BXH + boff);
                ldsm_x2t(bl, sb32 + V_BXL + boff);
                #pragma unroll
                for (int mt = 0; mt < 4; mt++) {
                    mma_bf16(acc[mt][nt], ah[mt], bh);
                    mma_bf16(acc[mt][nt], ah[mt], bl);
                    mma_bf16(acc[mt][nt], al[mt], bh);
                }
            }
        }
        __syncthreads();
    }

    // write vpart[b][k][d] (float2 stores, 32B per quad)
    float* vp = g_vpart + (size_t)b * KK * DD;
    #pragma unroll
    for (int mt = 0; mt < 4; mt++) {
        int k0 = mt * 16 + (lane >> 2);
        #pragma unroll
        for (int nt = 0; nt < 4; nt++) {
            int d = d0 + w * 32 + nt * 8 + (lane & 3) * 2;
            *(float2*)&vp[(size_t)k0 * DD + d]       = make_float2(acc[mt][nt][0], acc[mt][nt][1]);
            *(float2*)&vp[(size_t)(k0 + 8) * DD + d] = make_float2(acc[mt][nt][2], acc[mt][nt][3]);
        }
    }
}

// ---------------------------------------------------------------------------
// Kernel 3: finisher — subtract a_sum*clusters2, transpose to out[b][d][k],
// per-(b,k) norm^2. Grid (8 dgroups, B), 256 threads (8 warps = 8 k-rows each).
// ---------------------------------------------------------------------------
__global__ __launch_bounds__(256) void k_fin(float* __restrict__ out)
{
    __shared__ float sT[64][66];
    __shared__ float sN[64];
    const int b = blockIdx.y, dg = blockIdx.x;
    const int lane = threadIdx.x & 31, w = threadIdx.x >> 5;
    const float* vp = g_vpart + (size_t)b * KK * DD;

    #pragma unroll
    for (int kr = 0; kr < 8; kr++) {
        int k = w * 8 + kr;
        float as = g_asum[b * KK + k];
        int d = dg * 64 + lane;
        float v0 = vp[(size_t)k * DD + d]      - as * g_c2T[k * DD + d];
        float v1 = vp[(size_t)k * DD + d + 32] - as * g_c2T[k * DD + d + 32];
        sT[lane][k]      = v0;
        sT[lane + 32][k] = v1;
        float n2 = v0 * v0 + v1 * v1;
        #pragma unroll
        for (int o = 16; o >= 1; o >>= 1) n2 += __shfl_xor_sync(0xffffffffu, n2, o);
        if (lane == 0) sN[k] = n2;
    }
    __syncthreads();
    if (threadIdx.x < KK)
        atomicAdd(&g_norm2[b * KK + threadIdx.x], sN[threadIdx.x]);
    #pragma unroll
    for (int j = 0; j < 16; j++) {
        int idx = threadIdx.x + j * 256;
        int d = idx >> 6, k = idx & 63;
        out[((size_t)b * DD + dg * 64 + d) * KK + k] = sT[d][k];
    }
}

// ---------------------------------------------------------------------------
// Kernel 4: per-(b,k) combined scale
// ---------------------------------------------------------------------------
__global__ void k_colscale() {
    int b = blockIdx.x;
    int k = threadIdx.x;
    float n2 = g_norm2[b * KK + k];
    float nr = sqrtf(n2);
    float inv = 1.0f / fmaxf(nr, 1e-12f);
    float c = n2 * inv * inv;
    __shared__ float sh[2];
    #pragma unroll
    for (int o = 16; o >= 1; o >>= 1) c += __shfl_xor_sync(0xffffffffu, c, o);
    if ((threadIdx.x & 31) == 0) sh[threadIdx.x >> 5] = c;
    __syncthreads();
    float tot = sqrtf(sh[0] + sh[1]);
    float invt = 1.0f / fmaxf(tot, 1e-12f);
    g_scale[b * KK + k] = inv * invt;
}

// ---------------------------------------------------------------------------
// Kernel 5: in-place scale of d_out
// ---------------------------------------------------------------------------
__global__ void k_out(float* __restrict__ out) {
    int i = blockIdx.x * 256 + threadIdx.x;
    int b = i >> 15;
    int k = i & 63;
    out[i] = out[i] * g_scale[(b << 6) + k];
}

// ---------------------------------------------------------------------------
extern "C" void kernel_launch(void* const* d_in, const int* in_sizes, int n_in,
                              void* d_out, int out_size) {
    const float* x         = (const float*)d_in[0];
    const float* clusters  = (const float*)d_in[1];
    const float* clusters2 = (const float*)d_in[2];
    const float* bnw       = (const float*)d_in[3];
    const float* bnb       = (const float*)d_in[4];
    const float* rm        = (const float*)d_in[5];
    const float* rv        = (const float*)d_in[6];
    float* out = (float*)d_out;

    cudaFuncSetAttribute(k_logits_mma, cudaFuncAttributeMaxDynamicSharedMemorySize, L_SMEM);

    k_zero<<<(BB * KK + 255) / 256, 256>>>();
    k_prep<<<(DD * KGC + 255) / 256, 256>>>(clusters);
    k_prep2<<<KK, DD>>>(clusters2);
    dim3 g1(NN / 128, BB);
    k_logits_mma<<<g1, 128, L_SMEM>>>(x, bnw, bnb, rm, rv);
    dim3 g2(DD / 128, BB);
    k_vlad_mma<<<g2, 128>>>(x);
    dim3 g3(8, BB);
    k_fin<<<g3, 256>>>(out);
    k_colscale<<<BB, KK>>>();
    k_out<<<(BB * DD * KK) / 256, 256>>>(out);
}

// round 6
// speedup vs baseline: 3.5032x; 1.3244x over previous
#include <cuda_runtime.h>
#include <cuda_bf16.h>
#include <cstdint>

#define BB 64
#define NN 2048
#define DD 512
#define KK 64
#define KGC 80

// Scratch (device globals — no allocation allowed)
__device__ __nv_bfloat16 g_aThi[(size_t)BB * KK * NN];   // assignment^T hi [b][k][n]
__device__ __nv_bfloat16 g_aTlo[(size_t)BB * KK * NN];   // assignment^T lo
__device__ float g_vpart[2][(size_t)BB * KK * DD];       // vlad partials [chunk][b][k][d]
__device__ float g_asum[BB * KK];
__device__ float g_norm2[BB * KK];
__device__ float g_scale[BB * KK];
__device__ __nv_bfloat16 g_cHi[DD * KGC];                // clusters hi split [d][c]
__device__ __nv_bfloat16 g_cLo[DD * KGC];                // clusters lo split
__device__ float g_c2T[KK * DD];                         // clusters2^T [k][d]

// ===================== mma.sync / ldmatrix helpers =====================
__device__ __forceinline__ uint32_t smem_to_u32(const void* p) {
    uint32_t a;
    asm("{ .reg .u64 t; cvta.to.shared.u64 t, %1; cvt.u32.u64 %0, t; }" : "=r"(a) : "l"(p));
    return a;
}
__device__ __forceinline__ void mma_bf16(float* c, const uint32_t* a, const uint32_t* b) {
    asm volatile("mma.sync.aligned.m16n8k16.row.col.f32.bf16.bf16.f32 "
        "{%0,%1,%2,%3}, {%4,%5,%6,%7}, {%8,%9}, {%0,%1,%2,%3};"
        : "+f"(c[0]), "+f"(c[1]), "+f"(c[2]), "+f"(c[3])
        : "r"(a[0]), "r"(a[1]), "r"(a[2]), "r"(a[3]), "r"(b[0]), "r"(b[1]));
}
__device__ __forceinline__ void ldsm_x4(uint32_t* r, uint32_t addr) {
    asm volatile("ldmatrix.sync.aligned.m8n8.x4.shared.b16 {%0,%1,%2,%3}, [%4];"
        : "=r"(r[0]), "=r"(r[1]), "=r"(r[2]), "=r"(r[3]) : "r"(addr));
}
__device__ __forceinline__ void ldsm_x2t(uint32_t* r, uint32_t addr) {
    asm volatile("ldmatrix.sync.aligned.m8n8.x2.trans.shared.b16 {%0,%1}, [%2];"
        : "=r"(r[0]), "=r"(r[1]) : "r"(addr));
}
__device__ __forceinline__ void split2(float2 v, uint32_t& hi, uint32_t& lo) {
    __nv_bfloat162 h = __float22bfloat162_rn(v);
    float2 hf = __bfloat1622float2(h);
    __nv_bfloat162 l = __float22bfloat162_rn(make_float2(v.x - hf.x, v.y - hf.y));
    hi = *(uint32_t*)&h;
    lo = *(uint32_t*)&l;
}

// ---------------------------------------------------------------------------
// Kernel 0: zero accumulators
// ---------------------------------------------------------------------------
__global__ void k_zero() {
    int i = blockIdx.x * 256 + threadIdx.x;
    if (i < BB * KK) { g_asum[i] = 0.0f; g_norm2[i] = 0.0f; }
}

// ---------------------------------------------------------------------------
// Kernel P1: split clusters [512][80] into bf16 hi/lo
// ---------------------------------------------------------------------------
__global__ void k_prep(const float* __restrict__ clusters) {
    int i = blockIdx.x * 256 + threadIdx.x;
    if (i < DD * KGC) {
        float v = clusters[i];
        __nv_bfloat16 h = __float2bfloat16(v);
        g_cHi[i] = h;
        g_cLo[i] = __float2bfloat16(v - __bfloat162float(h));
    }
}
// Kernel P2: transpose clusters2 [512][64] -> [64][512]
__global__ void k_prep2(const float* __restrict__ clusters2) {
    int k = blockIdx.x;
    int d = threadIdx.x;
    g_c2T[k * DD + d] = clusters2[d * KK + k];
}

// ---------------------------------------------------------------------------
// Kernel 1: logits GEMM (mma.sync bf16x3) + BN + softmax + a_sum + assignT
// CTA: 256 threads (8 warps, M-split 16 rows each), tile M=128 x N=80, K=512
// in 8 smem chunks. 2 CTAs/SM (128 reg cap) -> 16 warps/SM.
// ---------------------------------------------------------------------------
#define L_SAH 0          // x hi:   [128][72] bf16, 144B stride -> 18432B
#define L_SAL 18432      // x lo
#define L_SBH 36864      // c hi:   [64][88] bf16, 176B stride -> 11264B
#define L_SBL 48128      // c lo
#define L_BN  59392      // 240 floats
#define L_AS  60352      // 256 floats
#define L_SMEM 61376

__global__ __launch_bounds__(256, 2) void k_logits_mma(
    const float* __restrict__ x,
    const float* __restrict__ bnw, const float* __restrict__ bnb,
    const float* __restrict__ rm, const float* __restrict__ rv)
{
    extern __shared__ __align__(16) char smem[];
    const int tid = threadIdx.x;
    const int lane = tid & 31, w = tid >> 5;          // 8 warps
    const int b = blockIdx.y, n0 = blockIdx.x * 128;
    const float* xb = x + ((size_t)b * NN + n0) * DD;
    uint32_t sb32 = smem_to_u32(smem);

    float* sScale = (float*)(smem + L_BN);
    float* sRm = sScale + 80;
    float* sBb = sScale + 160;
    if (tid < KGC) {
        sScale[tid] = bnw[tid] * rsqrtf(rv[tid] + 1e-5f);
        sRm[tid] = rm[tid];
        sBb[tid] = bnb[tid];
    }

    float acc[10][4];
    #pragma unroll
    for (int nt = 0; nt < 10; nt++)
        #pragma unroll
        for (int e = 0; e < 4; e++) acc[nt][e] = 0.f;

    const int arow = w * 16 + (lane & 15);       // ldmatrix A row
    const int acol = (lane >> 4) * 8;            // ldmatrix A col offset
    const int brow = lane & 15;

    for (int dt = 0; dt < 8; dt++) {
        // ---- stage x chunk [128 n][64 d] fp32 -> bf16 hi/lo ----
        #pragma unroll
        for (int j = 0; j < 8; j++) {
            int fidx = tid + j * 256;            // 0..2047 float4s
            int r = fidx >> 4, u = fidx & 15;
            float4 v = *(const float4*)&xb[(size_t)r * DD + dt * 64 + u * 4];
            uint32_t h0, l0, h1, l1;
            split2(make_float2(v.x, v.y), h0, l0);
            split2(make_float2(v.z, v.w), h1, l1);
            int off = r * 144 + u * 8;
            *(uint2*)(smem + L_SAH + off) = make_uint2(h0, h1);
            *(uint2*)(smem + L_SAL + off) = make_uint2(l0, l1);
        }
        // ---- stage clusters chunk [64 d][80 c] bf16 ----
        #pragma unroll
        for (int j = 0; j < 3; j++) {
            int idx = tid + j * 256;             // 0..639 16B units
            if (idx < 640) {
                int r = idx / 10, u = idx - r * 10;
                size_t ge = (size_t)(dt * 64 + r) * KGC + u * 8;
                uint4 vh = *(const uint4*)(g_cHi + ge);
                uint4 vl = *(const uint4*)(g_cLo + ge);
                int off = r * 176 + u * 16;
                *(uint4*)(smem + L_SBH + off) = vh;
                *(uint4*)(smem + L_SBL + off) = vl;
            }
        }
        __syncthreads();

        #pragma unroll
        for (int kt = 0; kt < 4; kt++) {
            uint32_t ah[4], al[4];
            uint32_t aoff = (uint32_t)(arow * 144 + (kt * 16 + acol) * 2);
            ldsm_x4(ah, sb32 + L_SAH + aoff);
            ldsm_x4(al, sb32 + L_SAL + aoff);
            #pragma unroll
            for (int nt = 0; nt < 10; nt++) {
                uint32_t boff = (uint32_t)((kt * 16 + brow) * 176 + nt * 16);
                uint32_t bh[2], bl[2];
                ldsm_x2t(bh, sb32 + L_SBH + boff);
                ldsm_x2t(bl, sb32 + L_SBL + boff);
                mma_bf16(acc[nt], ah, bh);
                mma_bf16(acc[nt], ah, bl);
                mma_bf16(acc[nt], al, bh);
            }
        }
        __syncthreads();
    }

    // ---- BN affine ----
    #pragma unroll
    for (int nt = 0; nt < 10; nt++) {
        int c0 = nt * 8 + (lane & 3) * 2;
        float s0 = sScale[c0], s1 = sScale[c0 + 1];
        float m0 = sRm[c0],    m1 = sRm[c0 + 1];
        float q0 = sBb[c0],    q1 = sBb[c0 + 1];
        acc[nt][0] = (acc[nt][0] - m0) * s0 + q0;
        acc[nt][1] = (acc[nt][1] - m1) * s1 + q1;
        acc[nt][2] = (acc[nt][2] - m0) * s0 + q0;
        acc[nt][3] = (acc[nt][3] - m1) * s1 + q1;
    }

    // ---- softmax per row (quad of 4 lanes holds one row, 20 cols each) ----
    float* sOut = (float*)smem;                  // reuse A region: [128][66]
    #pragma unroll
    for (int h = 0; h < 2; h++) {
        float mx = -3.4e38f;
        #pragma unroll
        for (int nt = 0; nt < 10; nt++)
            mx = fmaxf(mx, fmaxf(acc[nt][h * 2], acc[nt][h * 2 + 1]));
        mx = fmaxf(mx, __shfl_xor_sync(0xffffffffu, mx, 1));
        mx = fmaxf(mx, __shfl_xor_sync(0xffffffffu, mx, 2));
        float e[10][2];
        float sum = 0.f;
        #pragma unroll
        for (int nt = 0; nt < 10; nt++) {
            e[nt][0] = __expf(acc[nt][h * 2] - mx);
            e[nt][1] = __expf(acc[nt][h * 2 + 1] - mx);
            sum += e[nt][0] + e[nt][1];
        }
        sum += __shfl_xor_sync(0xffffffffu, sum, 1);
        sum += __shfl_xor_sync(0xffffffffu, sum, 2);
        float inv = 1.0f / sum;
        int row = w * 16 + h * 8 + (lane >> 2);
        #pragma unroll
        for (int nt = 0; nt < 8; nt++) {         // only first 64 cols kept
            float2 v = make_float2(e[nt][0] * inv, e[nt][1] * inv);
            *(float2*)&sOut[row * 66 + nt * 8 + (lane & 3) * 2] = v;
        }
    }
    __syncthreads();

    // ---- a_sum ----
    float* sAs = (float*)(smem + L_AS);
    {
        int k = tid & 63, q = tid >> 6;          // 4 quarters x 32 rows
        float s = 0.f;
        #pragma unroll 8
        for (int r = q * 32; r < q * 32 + 32; r++) s += sOut[r * 66 + k];
        sAs[q * 64 + k] = s;
    }
    __syncthreads();
    if (tid < KK)
        atomicAdd(&g_asum[b * KK + tid],
                  sAs[tid] + sAs[64 + tid] + sAs[128 + tid] + sAs[192 + tid]);

    // ---- assignment^T as bf16 hi/lo: coalesced in n ----
    {
        int row = tid & 127, kh = (tid >> 7) * 32;   // two k-halves
        __nv_bfloat16* aThi = g_aThi + (size_t)b * KK * NN + n0 + row;
        __nv_bfloat16* aTlo = g_aTlo + (size_t)b * KK * NN + n0 + row;
        #pragma unroll 4
        for (int kk2 = 0; kk2 < 32; kk2++) {
            int k = kh + kk2;
            float v = sOut[row * 66 + k];
            __nv_bfloat16 h = __float2bfloat16(v);
            aThi[(size_t)k * NN] = h;
            aTlo[(size_t)k * NN] = __float2bfloat16(v - __bfloat162float(h));
        }
    }
}

// ---------------------------------------------------------------------------
// Kernel 2: vlad GEMM (mma.sync bf16x3): D[k_clu][d] = assign^T @ x
// CTA: 256 threads (8 warps = 2 M-split x 4 N-split), tile M=64 x N=128 d,
// K(n)=1024 per chunk (2 chunks). Writes partials to g_vpart[chunk].
// ---------------------------------------------------------------------------
#define V_BXH 0          // x hi: [32][136] bf16, 272B stride -> 8704B
#define V_BXL 8704
#define V_ATH 17408      // aT hi: [64][40] bf16, 80B stride -> 5120B
#define V_ATL 22528      // -> 27648B total

__global__ __launch_bounds__(256, 2) void k_vlad_mma(const float* __restrict__ x)
{
    __shared__ __align__(16) char sm[27648];
    const int tid = threadIdx.x, lane = tid & 31, w = tid >> 5;
    const int wm = w & 1, wn = w >> 1;           // M half (32 k), N quarter (32 d)
    const int b = blockIdx.z, chunk = blockIdx.y, d0 = blockIdx.x * 128;
    const float* xb = x + (size_t)b * NN * DD + d0;
    const __nv_bfloat16* aThi = g_aThi + (size_t)b * KK * NN;
    const __nv_bfloat16* aTlo = g_aTlo + (size_t)b * KK * NN;
    uint32_t sb32 = smem_to_u32(sm);

    float acc[2][4][4];
    #pragma unroll
    for (int mt = 0; mt < 2; mt++)
        #pragma unroll
        for (int nt = 0; nt < 4; nt++)
            #pragma unroll
            for (int e = 0; e < 4; e++) acc[mt][nt][e] = 0.f;

    for (int nc = 0; nc < 32; nc++) {
        const int nbase = chunk * 1024 + nc * 32;
        // x tile [32 n][128 d] fp32 -> bf16 hi/lo
        #pragma unroll
        for (int j = 0; j < 4; j++) {
            int idx = tid + j * 256;
            int r = idx >> 5, u = idx & 31;
            float4 v = *(const float4*)&xb[(size_t)(nbase + r) * DD + u * 4];
            uint32_t h0, l0, h1, l1;
            split2(make_float2(v.x, v.y), h0, l0);
            split2(make_float2(v.z, v.w), h1, l1);
            int off = r * 272 + u * 8;
            *(uint2*)(sm + V_BXH + off) = make_uint2(h0, h1);
            *(uint2*)(sm + V_BXL + off) = make_uint2(l0, l1);
        }
        // aT tile [64 k][32 n] bf16 hi/lo (1 iter: 256 16B units)
        {
            int r = tid >> 2, u = tid & 3;
            size_t ge = (size_t)r * NN + nbase + u * 8;
            uint4 vh = *(const uint4*)(aThi + ge);
            uint4 vl = *(const uint4*)(aTlo + ge);
            int off = r * 80 + u * 16;
            *(uint4*)(sm + V_ATH + off) = vh;
            *(uint4*)(sm + V_ATL + off) = vl;
        }
        __syncthreads();

        #pragma unroll
        for (int kt = 0; kt < 2; kt++) {
            uint32_t ah[2][4], al[2][4];
            #pragma unroll
            for (int mt = 0; mt < 2; mt++) {
                uint32_t aoff = (uint32_t)((wm * 32 + mt * 16 + (lane & 15)) * 80 +
                                           (kt * 16 + (lane >> 4) * 8) * 2);
                ldsm_x4(ah[mt], sb32 + V_ATH + aoff);
                ldsm_x4(al[mt], sb32 + V_ATL + aoff);
            }
            #pragma unroll
            for (int nt = 0; nt < 4; nt++) {
                uint32_t boff = (uint32_t)((kt * 16 + (lane & 15)) * 272 +
                                           (wn * 32 + nt * 8) * 2);
                uint32_t bh[2], bl[2];
                ldsm_x2t(bh, sb32 + V_BXH + boff);
                ldsm_x2t(bl, sb32 + V_BXL + boff);
                #pragma unroll
                for (int mt = 0; mt < 2; mt++) {
                    mma_bf16(acc[mt][nt], ah[mt], bh);
                    mma_bf16(acc[mt][nt], ah[mt], bl);
                    mma_bf16(acc[mt][nt], al[mt], bh);
                }
            }
        }
        __syncthreads();
    }

    float* vp = g_vpart[chunk] + (size_t)b * KK * DD;
    #pragma unroll
    for (int mt = 0; mt < 2; mt++) {
        int k0 = wm * 32 + mt * 16 + (lane >> 2);
        #pragma unroll
        for (int nt = 0; nt < 4; nt++) {
            int d = d0 + wn * 32 + nt * 8 + (lane & 3) * 2;
            *(float2*)&vp[(size_t)k0 * DD + d]       = make_float2(acc[mt][nt][0], acc[mt][nt][1]);
            *(float2*)&vp[(size_t)(k0 + 8) * DD + d] = make_float2(acc[mt][nt][2], acc[mt][nt][3]);
        }
    }
}

// ---------------------------------------------------------------------------
// Kernel 3: finisher — sum partials, subtract a_sum*clusters2, transpose to
// out[b][d][k], per-(b,k) norm^2. Grid (8 dgroups, B), 256 threads.
// ---------------------------------------------------------------------------
__global__ __launch_bounds__(256) void k_fin(float* __restrict__ out)
{
    __shared__ float sT[64][66];
    __shared__ float sN[64];
    const int b = blockIdx.y, dg = blockIdx.x;
    const int lane = threadIdx.x & 31, w = threadIdx.x >> 5;
    const float* vp0 = g_vpart[0] + (size_t)b * KK * DD;
    const float* vp1 = g_vpart[1] + (size_t)b * KK * DD;

    #pragma unroll
    for (int kr = 0; kr < 8; kr++) {
        int k = w * 8 + kr;
        float as = g_asum[b * KK + k];
        int d = dg * 64 + lane;
        float v0 = vp0[(size_t)k * DD + d]      + vp1[(size_t)k * DD + d]
                 - as * g_c2T[k * DD + d];
        float v1 = vp0[(size_t)k * DD + d + 32] + vp1[(size_t)k * DD + d + 32]
                 - as * g_c2T[k * DD + d + 32];
        sT[lane][k]      = v0;
        sT[lane + 32][k] = v1;
        float n2 = v0 * v0 + v1 * v1;
        #pragma unroll
        for (int o = 16; o >= 1; o >>= 1) n2 += __shfl_xor_sync(0xffffffffu, n2, o);
        if (lane == 0) sN[k] = n2;
    }
    __syncthreads();
    if (threadIdx.x < KK)
        atomicAdd(&g_norm2[b * KK + threadIdx.x], sN[threadIdx.x]);
    #pragma unroll
    for (int j = 0; j < 16; j++) {
        int idx = threadIdx.x + j * 256;
        int d = idx >> 6, k = idx & 63;
        out[((size_t)b * DD + dg * 64 + d) * KK + k] = sT[d][k];
    }
}

// ---------------------------------------------------------------------------
// Kernel 4: per-(b,k) combined scale
// ---------------------------------------------------------------------------
__global__ void k_colscale() {
    int b = blockIdx.x;
    int k = threadIdx.x;
    float n2 = g_norm2[b * KK + k];
    float nr = sqrtf(n2);
    float inv = 1.0f / fmaxf(nr, 1e-12f);
    float c = n2 * inv * inv;
    __shared__ float sh[2];
    #pragma unroll
    for (int o = 16; o >= 1; o >>= 1) c += __shfl_xor_sync(0xffffffffu, c, o);
    if ((threadIdx.x & 31) == 0) sh[threadIdx.x >> 5] = c;
    __syncthreads();
    float tot = sqrtf(sh[0] + sh[1]);
    float invt = 1.0f / fmaxf(tot, 1e-12f);
    g_scale[b * KK + k] = inv * invt;
}

// ---------------------------------------------------------------------------
// Kernel 5: in-place scale of d_out
// ---------------------------------------------------------------------------
__global__ void k_out(float* __restrict__ out) {
    int i = blockIdx.x * 256 + threadIdx.x;
    int b = i >> 15;
    int k = i & 63;
    out[i] = out[i] * g_scale[(b << 6) + k];
}

// ---------------------------------------------------------------------------
extern "C" void kernel_launch(void* const* d_in, const int* in_sizes, int n_in,
                              void* d_out, int out_size) {
    const float* x         = (const float*)d_in[0];
    const float* clusters  = (const float*)d_in[1];
    const float* clusters2 = (const float*)d_in[2];
    const float* bnw       = (const float*)d_in[3];
    const float* bnb       = (const float*)d_in[4];
    const float* rm        = (const float*)d_in[5];
    const float* rv        = (const float*)d_in[6];
    float* out = (float*)d_out;

    cudaFuncSetAttribute(k_logits_mma, cudaFuncAttributeMaxDynamicSharedMemorySize, L_SMEM);

    k_zero<<<(BB * KK + 255) / 256, 256>>>();
    k_prep<<<(DD * KGC + 255) / 256, 256>>>(clusters);
    k_prep2<<<KK, DD>>>(clusters2);
    dim3 g1(NN / 128, BB);
    k_logits_mma<<<g1, 256, L_SMEM>>>(x, bnw, bnb, rm, rv);
    dim3 g2(DD / 128, 2, BB);
    k_vlad_mma<<<g2, 256>>>(x);
    dim3 g3(8, BB);
    k_fin<<<g3, 256>>>(out);
    k_colscale<<<BB, KK>>>();
    k_out<<<(BB * DD * KK) / 256, 256>>>(out);
}

// round 7
// speedup vs baseline: 3.5491x; 1.0131x over previous
#include <cuda_runtime.h>
#include <cuda_bf16.h>
#include <cstdint>

#define BB 64
#define NN 2048
#define DD 512
#define KK 64
#define KGC 80

// Scratch (device globals — no allocation allowed)
__device__ __nv_bfloat16 g_aThi[(size_t)BB * KK * NN];   // assignment^T hi [b][k][n]
__device__ __nv_bfloat16 g_aTlo[(size_t)BB * KK * NN];   // assignment^T lo
__device__ float g_vpart[2][(size_t)BB * KK * DD];       // vlad partials [chunk][b][k][d]
__device__ float g_asum[BB * KK];
__device__ float g_norm2[BB * KK];
__device__ float g_scale[BB * KK];
__device__ __nv_bfloat16 g_cHi[DD * KGC];                // clusters hi split [d][c]
__device__ __nv_bfloat16 g_cLo[DD * KGC];                // clusters lo split
__device__ float g_c2T[KK * DD];                         // clusters2^T [k][d]

// ===================== mma.sync / ldmatrix helpers =====================
__device__ __forceinline__ uint32_t smem_to_u32(const void* p) {
    uint32_t a;
    asm("{ .reg .u64 t; cvta.to.shared.u64 t, %1; cvt.u32.u64 %0, t; }" : "=r"(a) : "l"(p));
    return a;
}
__device__ __forceinline__ void mma_bf16(float* c, const uint32_t* a, const uint32_t* b) {
    asm volatile("mma.sync.aligned.m16n8k16.row.col.f32.bf16.bf16.f32 "
        "{%0,%1,%2,%3}, {%4,%5,%6,%7}, {%8,%9}, {%0,%1,%2,%3};"
        : "+f"(c[0]), "+f"(c[1]), "+f"(c[2]), "+f"(c[3])
        : "r"(a[0]), "r"(a[1]), "r"(a[2]), "r"(a[3]), "r"(b[0]), "r"(b[1]));
}
__device__ __forceinline__ void ldsm_x4(uint32_t* r, uint32_t addr) {
    asm volatile("ldmatrix.sync.aligned.m8n8.x4.shared.b16 {%0,%1,%2,%3}, [%4];"
        : "=r"(r[0]), "=r"(r[1]), "=r"(r[2]), "=r"(r[3]) : "r"(addr));
}
__device__ __forceinline__ void ldsm_x4t(uint32_t* r, uint32_t addr) {
    asm volatile("ldmatrix.sync.aligned.m8n8.x4.trans.shared.b16 {%0,%1,%2,%3}, [%4];"
        : "=r"(r[0]), "=r"(r[1]), "=r"(r[2]), "=r"(r[3]) : "r"(addr));
}
__device__ __forceinline__ void ldsm_x2t(uint32_t* r, uint32_t addr) {
    asm volatile("ldmatrix.sync.aligned.m8n8.x2.trans.shared.b16 {%0,%1}, [%2];"
        : "=r"(r[0]), "=r"(r[1]) : "r"(addr));
}
__device__ __forceinline__ void split2(float2 v, uint32_t& hi, uint32_t& lo) {
    __nv_bfloat162 h = __float22bfloat162_rn(v);
    float2 hf = __bfloat1622float2(h);
    __nv_bfloat162 l = __float22bfloat162_rn(make_float2(v.x - hf.x, v.y - hf.y));
    hi = *(uint32_t*)&h;
    lo = *(uint32_t*)&l;
}

// ---------------------------------------------------------------------------
// Kernel 0: zero accumulators
// ---------------------------------------------------------------------------
__global__ void k_zero() {
    int i = blockIdx.x * 256 + threadIdx.x;
    if (i < BB * KK) { g_asum[i] = 0.0f; g_norm2[i] = 0.0f; }
}

// ---------------------------------------------------------------------------
// Kernel P1: split clusters [512][80] into bf16 hi/lo
// ---------------------------------------------------------------------------
__global__ void k_prep(const float* __restrict__ clusters) {
    int i = blockIdx.x * 256 + threadIdx.x;
    if (i < DD * KGC) {
        float v = clusters[i];
        __nv_bfloat16 h = __float2bfloat16(v);
        g_cHi[i] = h;
        g_cLo[i] = __float2bfloat16(v - __bfloat162float(h));
    }
}
// Kernel P2: transpose clusters2 [512][64] -> [64][512]
__global__ void k_prep2(const float* __restrict__ clusters2) {
    int k = blockIdx.x;
    int d = threadIdx.x;
    g_c2T[k * DD + d] = clusters2[d * KK + k];
}

// ---------------------------------------------------------------------------
// Kernel 1: logits GEMM (mma.sync bf16x3) + BN + softmax + a_sum + assignT
// CTA: 256 threads = 8 warps, 4 M-split x 2 N-split (warp tile 32 rows x 40
// cols). Tile M=128 x N=80, K=512 in 8 smem chunks. 2 CTAs/SM.
// ---------------------------------------------------------------------------
#define L_SAH 0          // x hi:   [128][72] bf16, 144B stride -> 18432B
#define L_SAL 18432      // x lo
#define L_SBH 36864      // c hi:   [64][88] bf16, 176B stride -> 11264B
#define L_SBL 48128      // c lo
#define L_BN  59392      // 240 floats -> 960B
#define L_AS  60352      // 256 floats -> 1024B
#define L_PM  61376      // 256 floats (row-partial max [row][wn])
#define L_PS  62400      // 256 floats (row-partial sum)
#define L_SMEM 63424

__global__ __launch_bounds__(256, 2) void k_logits_mma(
    const float* __restrict__ x,
    const float* __restrict__ bnw, const float* __restrict__ bnb,
    const float* __restrict__ rm, const float* __restrict__ rv)
{
    extern __shared__ __align__(16) char smem[];
    const int tid = threadIdx.x;
    const int lane = tid & 31, w = tid >> 5;
    const int wm = w & 3, wn = w >> 2;           // 4 M-warps x 2 N-warps
    const int b = blockIdx.y, n0 = blockIdx.x * 128;
    const float* xb = x + ((size_t)b * NN + n0) * DD;
    uint32_t sb32 = smem_to_u32(smem);

    float* sScale = (float*)(smem + L_BN);
    float* sRm = sScale + 80;
    float* sBb = sScale + 160;
    if (tid < KGC) {
        sScale[tid] = bnw[tid] * rsqrtf(rv[tid] + 1e-5f);
        sRm[tid] = rm[tid];
        sBb[tid] = bnb[tid];
    }

    float acc[2][5][4];
    #pragma unroll
    for (int mt = 0; mt < 2; mt++)
        #pragma unroll
        for (int nt = 0; nt < 5; nt++)
            #pragma unroll
            for (int e = 0; e < 4; e++) acc[mt][nt][e] = 0.f;

    for (int dt = 0; dt < 8; dt++) {
        // ---- stage x chunk [128 n][64 d] fp32 -> bf16 hi/lo ----
        #pragma unroll
        for (int j = 0; j < 8; j++) {
            int fidx = tid + j * 256;
            int r = fidx >> 4, u = fidx & 15;
            float4 v = *(const float4*)&xb[(size_t)r * DD + dt * 64 + u * 4];
            uint32_t h0, l0, h1, l1;
            split2(make_float2(v.x, v.y), h0, l0);
            split2(make_float2(v.z, v.w), h1, l1);
            int off = r * 144 + u * 8;
            *(uint2*)(smem + L_SAH + off) = make_uint2(h0, h1);
            *(uint2*)(smem + L_SAL + off) = make_uint2(l0, l1);
        }
        // ---- stage clusters chunk [64 d][80 c] bf16 ----
        #pragma unroll
        for (int j = 0; j < 3; j++) {
            int idx = tid + j * 256;
            if (idx < 640) {
                int r = idx / 10, u = idx - r * 10;
                size_t ge = (size_t)(dt * 64 + r) * KGC + u * 8;
                uint4 vh = *(const uint4*)(g_cHi + ge);
                uint4 vl = *(const uint4*)(g_cLo + ge);
                int off = r * 176 + u * 16;
                *(uint4*)(smem + L_SBH + off) = vh;
                *(uint4*)(smem + L_SBL + off) = vl;
            }
        }
        __syncthreads();

        #pragma unroll
        for (int kt = 0; kt < 4; kt++) {
            uint32_t ah[2][4], al[2][4];
            #pragma unroll
            for (int mt = 0; mt < 2; mt++) {
                uint32_t aoff = (uint32_t)((wm * 32 + mt * 16 + (lane & 15)) * 144 +
                                           (kt * 16 + (lane >> 4) * 8) * 2);
                ldsm_x4(ah[mt], sb32 + L_SAH + aoff);
                ldsm_x4(al[mt], sb32 + L_SAL + aoff);
            }
            uint32_t bh[5][2], bl[5][2];
            #pragma unroll
            for (int p = 0; p < 2; p++) {        // nt pairs {0,1},{2,3} via x4.trans
                uint32_t t[4];
                uint32_t boff = (uint32_t)((kt * 16 + (lane & 15)) * 176 +
                                           (wn * 40 + p * 16 + (lane >> 4) * 8) * 2);
                ldsm_x4t(t, sb32 + L_SBH + boff);
                bh[2*p][0] = t[0]; bh[2*p][1] = t[1];
                bh[2*p+1][0] = t[2]; bh[2*p+1][1] = t[3];
                ldsm_x4t(t, sb32 + L_SBL + boff);
                bl[2*p][0] = t[0]; bl[2*p][1] = t[1];
                bl[2*p+1][0] = t[2]; bl[2*p+1][1] = t[3];
            }
            {
                uint32_t boff = (uint32_t)((kt * 16 + (lane & 15)) * 176 + (wn * 40 + 32) * 2);
                ldsm_x2t(bh[4], sb32 + L_SBH + boff);
                ldsm_x2t(bl[4], sb32 + L_SBL + boff);
            }
            #pragma unroll
            for (int nt = 0; nt < 5; nt++)
                #pragma unroll
                for (int mt = 0; mt < 2; mt++) {
                    mma_bf16(acc[mt][nt], ah[mt], bh[nt]);
                    mma_bf16(acc[mt][nt], ah[mt], bl[nt]);
                    mma_bf16(acc[mt][nt], al[mt], bh[nt]);
                }
        }
        __syncthreads();
    }

    // ---- BN affine (col = wn*40 + nt*8 + (lane&3)*2 + e) ----
    #pragma unroll
    for (int nt = 0; nt < 5; nt++) {
        int c0 = wn * 40 + nt * 8 + (lane & 3) * 2;
        float s0 = sScale[c0], s1 = sScale[c0 + 1];
        float m0 = sRm[c0],    m1 = sRm[c0 + 1];
        float q0 = sBb[c0],    q1 = sBb[c0 + 1];
        #pragma unroll
        for (int mt = 0; mt < 2; mt++) {
            acc[mt][nt][0] = (acc[mt][nt][0] - m0) * s0 + q0;
            acc[mt][nt][1] = (acc[mt][nt][1] - m1) * s1 + q1;
            acc[mt][nt][2] = (acc[mt][nt][2] - m0) * s0 + q0;
            acc[mt][nt][3] = (acc[mt][nt][3] - m1) * s1 + q1;
        }
    }

    // ---- softmax: rows split across 2 N-warps -> 2-pass smem reduction ----
    float* sPM = (float*)(smem + L_PM);
    float* sPS = (float*)(smem + L_PS);
    float* sOut = (float*)smem;                  // reuse A region: [128][66]

    #pragma unroll
    for (int h = 0; h < 4; h++) {                // mt = h>>1, half = h&1
        int mt = h >> 1, hh = h & 1;
        float mx = -3.4e38f;
        #pragma unroll
        for (int nt = 0; nt < 5; nt++)
            mx = fmaxf(mx, fmaxf(acc[mt][nt][hh * 2], acc[mt][nt][hh * 2 + 1]));
        mx = fmaxf(mx, __shfl_xor_sync(0xffffffffu, mx, 1));
        mx = fmaxf(mx, __shfl_xor_sync(0xffffffffu, mx, 2));
        int row = wm * 32 + mt * 16 + hh * 8 + (lane >> 2);
        if ((lane & 3) == 0) sPM[row * 2 + wn] = mx;
    }
    __syncthreads();
    #pragma unroll
    for (int h = 0; h < 4; h++) {
        int mt = h >> 1, hh = h & 1;
        int row = wm * 32 + mt * 16 + hh * 8 + (lane >> 2);
        float m = fmaxf(sPM[row * 2], sPM[row * 2 + 1]);
        float sum = 0.f;
        #pragma unroll
        for (int nt = 0; nt < 5; nt++) {
            float e0 = __expf(acc[mt][nt][hh * 2] - m);
            float e1 = __expf(acc[mt][nt][hh * 2 + 1] - m);
            acc[mt][nt][hh * 2] = e0;
            acc[mt][nt][hh * 2 + 1] = e1;
            sum += e0 + e1;
        }
        sum += __shfl_xor_sync(0xffffffffu, sum, 1);
        sum += __shfl_xor_sync(0xffffffffu, sum, 2);
        if ((lane & 3) == 0) sPS[row * 2 + wn] = sum;
    }
    __syncthreads();
    const int ntmax = wn ? 3 : 5;                // keep cols < 64 only
    #pragma unroll
    for (int h = 0; h < 4; h++) {
        int mt = h >> 1, hh = h & 1;
        int row = wm * 32 + mt * 16 + hh * 8 + (lane >> 2);
        float inv = 1.0f / (sPS[row * 2] + sPS[row * 2 + 1]);
        #pragma unroll
        for (int nt = 0; nt < 5; nt++) {
            if (nt < ntmax) {
                int col = wn * 40 + nt * 8 + (lane & 3) * 2;
                float2 v = make_float2(acc[mt][nt][hh * 2] * inv,
                                       acc[mt][nt][hh * 2 + 1] * inv);
                *(float2*)&sOut[row * 66 + col] = v;
            }
        }
    }
    __syncthreads();

    // ---- a_sum ----
    float* sAs = (float*)(smem + L_AS);
    {
        int k = tid & 63, q = tid >> 6;
        float s = 0.f;
        #pragma unroll 8
        for (int r = q * 32; r < q * 32 + 32; r++) s += sOut[r * 66 + k];
        sAs[q * 64 + k] = s;
    }
    __syncthreads();
    if (tid < KK)
        atomicAdd(&g_asum[b * KK + tid],
                  sAs[tid] + sAs[64 + tid] + sAs[128 + tid] + sAs[192 + tid]);

    // ---- assignment^T as bf16 hi/lo: coalesced in n ----
    {
        int row = tid & 127, kh = (tid >> 7) * 32;
        __nv_bfloat16* aThi = g_aThi + (size_t)b * KK * NN + n0 + row;
        __nv_bfloat16* aTlo = g_aTlo + (size_t)b * KK * NN + n0 + row;
        #pragma unroll 4
        for (int kk2 = 0; kk2 < 32; kk2++) {
            int k = kh + kk2;
            float v = sOut[row * 66 + k];
            __nv_bfloat16 h = __float2bfloat16(v);
            aThi[(size_t)k * NN] = h;
            aTlo[(size_t)k * NN] = __float2bfloat16(v - __bfloat162float(h));
        }
    }
}

// ---------------------------------------------------------------------------
// Kernel 2: vlad GEMM (mma.sync bf16x3): D[k_clu][d] = assign^T @ x
// CTA: 256 threads (8 warps = 2 M-split x 4 N-split), tile M=64 x N=128 d,
// K(n)=1024 per chunk (2 chunks). Writes partials to g_vpart[chunk].
// ---------------------------------------------------------------------------
#define V_BXH 0          // x hi: [32][136] bf16, 272B stride -> 8704B
#define V_BXL 8704
#define V_ATH 17408      // aT hi: [64][40] bf16, 80B stride -> 5120B
#define V_ATL 22528      // -> 27648B total

__global__ __launch_bounds__(256, 2) void k_vlad_mma(const float* __restrict__ x)
{
    __shared__ __align__(16) char sm[27648];
    const int tid = threadIdx.x, lane = tid & 31, w = tid >> 5;
    const int wm = w & 1, wn = w >> 1;           // M half (32 k), N quarter (32 d)
    const int b = blockIdx.z, chunk = blockIdx.y, d0 = blockIdx.x * 128;
    const float* xb = x + (size_t)b * NN * DD + d0;
    const __nv_bfloat16* aThi = g_aThi + (size_t)b * KK * NN;
    const __nv_bfloat16* aTlo = g_aTlo + (size_t)b * KK * NN;
    uint32_t sb32 = smem_to_u32(sm);

    float acc[2][4][4];
    #pragma unroll
    for (int mt = 0; mt < 2; mt++)
        #pragma unroll
        for (int nt = 0; nt < 4; nt++)
            #pragma unroll
            for (int e = 0; e < 4; e++) acc[mt][nt][e] = 0.f;

    for (int nc = 0; nc < 32; nc++) {
        const int nbase = chunk * 1024 + nc * 32;
        // x tile [32 n][128 d] fp32 -> bf16 hi/lo
        #pragma unroll
        for (int j = 0; j < 4; j++) {
            int idx = tid + j * 256;
            int r = idx >> 5, u = idx & 31;
            float4 v = *(const float4*)&xb[(size_t)(nbase + r) * DD + u * 4];
            uint32_t h0, l0, h1, l1;
            split2(make_float2(v.x, v.y), h0, l0);
            split2(make_float2(v.z, v.w), h1, l1);
            int off = r * 272 + u * 8;
            *(uint2*)(sm + V_BXH + off) = make_uint2(h0, h1);
            *(uint2*)(sm + V_BXL + off) = make_uint2(l0, l1);
        }
        // aT tile [64 k][32 n] bf16 hi/lo
        {
            int r = tid >> 2, u = tid & 3;
            size_t ge = (size_t)r * NN + nbase + u * 8;
            uint4 vh = *(const uint4*)(aThi + ge);
            uint4 vl = *(const uint4*)(aTlo + ge);
            int off = r * 80 + u * 16;
            *(uint4*)(sm + V_ATH + off) = vh;
            *(uint4*)(sm + V_ATL + off) = vl;
        }
        __syncthreads();

        #pragma unroll
        for (int kt = 0; kt < 2; kt++) {
            uint32_t ah[2][4], al[2][4];
            #pragma unroll
            for (int mt = 0; mt < 2; mt++) {
                uint32_t aoff = (uint32_t)((wm * 32 + mt * 16 + (lane & 15)) * 80 +
                                           (kt * 16 + (lane >> 4) * 8) * 2);
                ldsm_x4(ah[mt], sb32 + V_ATH + aoff);
                ldsm_x4(al[mt], sb32 + V_ATL + aoff);
            }
            uint32_t bh[4][2], bl[4][2];
            #pragma unroll
            for (int p = 0; p < 2; p++) {        // d-pairs via x4.trans
                uint32_t t[4];
                uint32_t boff = (uint32_t)((kt * 16 + (lane & 15)) * 272 +
                                           (wn * 32 + p * 16 + (lane >> 4) * 8) * 2);
                ldsm_x4t(t, sb32 + V_BXH + boff);
                bh[2*p][0] = t[0]; bh[2*p][1] = t[1];
                bh[2*p+1][0] = t[2]; bh[2*p+1][1] = t[3];
                ldsm_x4t(t, sb32 + V_BXL + boff);
                bl[2*p][0] = t[0]; bl[2*p][1] = t[1];
                bl[2*p+1][0] = t[2]; bl[2*p+1][1] = t[3];
            }
            #pragma unroll
            for (int nt = 0; nt < 4; nt++)
                #pragma unroll
                for (int mt = 0; mt < 2; mt++) {
                    mma_bf16(acc[mt][nt], ah[mt], bh[nt]);
                    mma_bf16(acc[mt][nt], ah[mt], bl[nt]);
                    mma_bf16(acc[mt][nt], al[mt], bh[nt]);
                }
        }
        __syncthreads();
    }

    float* vp = g_vpart[chunk] + (size_t)b * KK * DD;
    #pragma unroll
    for (int mt = 0; mt < 2; mt++) {
        int k0 = wm * 32 + mt * 16 + (lane >> 2);
        #pragma unroll
        for (int nt = 0; nt < 4; nt++) {
            int d = d0 + wn * 32 + nt * 8 + (lane & 3) * 2;
            *(float2*)&vp[(size_t)k0 * DD + d]       = make_float2(acc[mt][nt][0], acc[mt][nt][1]);
            *(float2*)&vp[(size_t)(k0 + 8) * DD + d] = make_float2(acc[mt][nt][2], acc[mt][nt][3]);
        }
    }
}

// ---------------------------------------------------------------------------
// Kernel 3: finisher — sum partials, subtract a_sum*clusters2, transpose to
// out[b][d][k], per-(b,k) norm^2. Grid (8 dgroups, B), 256 threads.
// ---------------------------------------------------------------------------
__global__ __launch_bounds__(256) void k_fin(float* __restrict__ out)
{
    __shared__ float sT[64][66];
    __shared__ float sN[64];
    const int b = blockIdx.y, dg = blockIdx.x;
    const int lane = threadIdx.x & 31, w = threadIdx.x >> 5;
    const float* vp0 = g_vpart[0] + (size_t)b * KK * DD;
    const float* vp1 = g_vpart[1] + (size_t)b * KK * DD;

    #pragma unroll
    for (int kr = 0; kr < 8; kr++) {
        int k = w * 8 + kr;
        float as = g_asum[b * KK + k];
        int d = dg * 64 + lane;
        float v0 = vp0[(size_t)k * DD + d]      + vp1[(size_t)k * DD + d]
                 - as * g_c2T[k * DD + d];
        float v1 = vp0[(size_t)k * DD + d + 32] + vp1[(size_t)k * DD + d + 32]
                 - as * g_c2T[k * DD + d + 32];
        sT[lane][k]      = v0;
        sT[lane + 32][k] = v1;
        float n2 = v0 * v0 + v1 * v1;
        #pragma unroll
        for (int o = 16; o >= 1; o >>= 1) n2 += __shfl_xor_sync(0xffffffffu, n2, o);
        if (lane == 0) sN[k] = n2;
    }
    __syncthreads();
    if (threadIdx.x < KK)
        atomicAdd(&g_norm2[b * KK + threadIdx.x], sN[threadIdx.x]);
    #pragma unroll
    for (int j = 0; j < 16; j++) {
        int idx = threadIdx.x + j * 256;
        int d = idx >> 6, k = idx & 63;
        out[((size_t)b * DD + dg * 64 + d) * KK + k] = sT[d][k];
    }
}

// ---------------------------------------------------------------------------
// Kernel 4: per-(b,k) combined scale
// ---------------------------------------------------------------------------
__global__ void k_colscale() {
    int b = blockIdx.x;
    int k = threadIdx.x;
    float n2 = g_norm2[b * KK + k];
    float nr = sqrtf(n2);
    float inv = 1.0f / fmaxf(nr, 1e-12f);
    float c = n2 * inv * inv;
    __shared__ float sh[2];
    #pragma unroll
    for (int o = 16; o >= 1; o >>= 1) c += __shfl_xor_sync(0xffffffffu, c, o);
    if ((threadIdx.x & 31) == 0) sh[threadIdx.x >> 5] = c;
    __syncthreads();
    float tot = sqrtf(sh[0] + sh[1]);
    float invt = 1.0f / fmaxf(tot, 1e-12f);
    g_scale[b * KK + k] = inv * invt;
}

// ---------------------------------------------------------------------------
// Kernel 5: in-place scale of d_out
// ---------------------------------------------------------------------------
__global__ void k_out(float* __restrict__ out) {
    int i = blockIdx.x * 256 + threadIdx.x;
    int b = i >> 15;
    int k = i & 63;
    out[i] = out[i] * g_scale[(b << 6) + k];
}

// ---------------------------------------------------------------------------
extern "C" void kernel_launch(void* const* d_in, const int* in_sizes, int n_in,
                              void* d_out, int out_size) {
    const float* x         = (const float*)d_in[0];
    const float* clusters  = (const float*)d_in[1];
    const float* clusters2 = (const float*)d_in[2];
    const float* bnw       = (const float*)d_in[3];
    const float* bnb       = (const float*)d_in[4];
    const float* rm        = (const float*)d_in[5];
    const float* rv        = (const float*)d_in[6];
    float* out = (float*)d_out;

    cudaFuncSetAttribute(k_logits_mma, cudaFuncAttributeMaxDynamicSharedMemorySize, L_SMEM);

    k_zero<<<(BB * KK + 255) / 256, 256>>>();
    k_prep<<<(DD * KGC + 255) / 256, 256>>>(clusters);
    k_prep2<<<KK, DD>>>(clusters2);
    dim3 g1(NN / 128, BB);
    k_logits_mma<<<g1, 256, L_SMEM>>>(x, bnw, bnb, rm, rv);
    dim3 g2(DD / 128, 2, BB);
    k_vlad_mma<<<g2, 256>>>(x);
    dim3 g3(8, BB);
    k_fin<<<g3, 256>>>(out);
    k_colscale<<<BB, KK>>>();
    k_out<<<(BB * DD * KK) / 256, 256>>>(out);
}

// round 8
// speedup vs baseline: 4.0517x; 1.1416x over previous
#include <cuda_runtime.h>
#include <cuda_bf16.h>
#include <cstdint>

#define BB 64
#define NN 2048
#define DD 512
#define KK 64
#define KGC 80

// Scratch (device globals — no allocation allowed)
__device__ __nv_bfloat16 g_aThi[(size_t)BB * KK * NN];   // assignment^T hi [b][k][n]
__device__ __nv_bfloat16 g_aTlo[(size_t)BB * KK * NN];   // assignment^T lo
__device__ float g_vpart[2][(size_t)BB * KK * DD];       // vlad partials [chunk][b][k][d]
__device__ float g_asum[BB * KK];
__device__ float g_norm2[BB * KK];
__device__ float g_scale[BB * KK];
__device__ __nv_bfloat16 g_cHi[DD * KGC];                // clusters hi split [d][c]
__device__ __nv_bfloat16 g_cLo[DD * KGC];                // clusters lo split
__device__ float g_c2T[KK * DD];                         // clusters2^T [k][d]

// ===================== mma.sync / ldmatrix helpers =====================
__device__ __forceinline__ uint32_t smem_to_u32(const void* p) {
    uint32_t a;
    asm("{ .reg .u64 t; cvta.to.shared.u64 t, %1; cvt.u32.u64 %0, t; }" : "=r"(a) : "l"(p));
    return a;
}
__device__ __forceinline__ void mma_bf16(float* c, const uint32_t* a, const uint32_t* b) {
    asm volatile("mma.sync.aligned.m16n8k16.row.col.f32.bf16.bf16.f32 "
        "{%0,%1,%2,%3}, {%4,%5,%6,%7}, {%8,%9}, {%0,%1,%2,%3};"
        : "+f"(c[0]), "+f"(c[1]), "+f"(c[2]), "+f"(c[3])
        : "r"(a[0]), "r"(a[1]), "r"(a[2]), "r"(a[3]), "r"(b[0]), "r"(b[1]));
}
__device__ __forceinline__ void ldsm_x4(uint32_t* r, uint32_t addr) {
    asm volatile("ldmatrix.sync.aligned.m8n8.x4.shared.b16 {%0,%1,%2,%3}, [%4];"
        : "=r"(r[0]), "=r"(r[1]), "=r"(r[2]), "=r"(r[3]) : "r"(addr));
}
__device__ __forceinline__ void ldsm_x4t(uint32_t* r, uint32_t addr) {
    asm volatile("ldmatrix.sync.aligned.m8n8.x4.trans.shared.b16 {%0,%1,%2,%3}, [%4];"
        : "=r"(r[0]), "=r"(r[1]), "=r"(r[2]), "=r"(r[3]) : "r"(addr));
}
__device__ __forceinline__ void ldsm_x2t(uint32_t* r, uint32_t addr) {
    asm volatile("ldmatrix.sync.aligned.m8n8.x2.trans.shared.b16 {%0,%1}, [%2];"
        : "=r"(r[0]), "=r"(r[1]) : "r"(addr));
}
__device__ __forceinline__ void split2(float2 v, uint32_t& hi, uint32_t& lo) {
    __nv_bfloat162 h = __float22bfloat162_rn(v);
    float2 hf = __bfloat1622float2(h);
    __nv_bfloat162 l = __float22bfloat162_rn(make_float2(v.x - hf.x, v.y - hf.y));
    hi = *(uint32_t*)&h;
    lo = *(uint32_t*)&l;
}

// ---------------------------------------------------------------------------
// Kernel 0: zero accumulators
// ---------------------------------------------------------------------------
__global__ void k_zero() {
    int i = blockIdx.x * 256 + threadIdx.x;
    if (i < BB * KK) { g_asum[i] = 0.0f; g_norm2[i] = 0.0f; }
}

// ---------------------------------------------------------------------------
// Kernel P1: split clusters [512][80] into bf16 hi/lo
// ---------------------------------------------------------------------------
__global__ void k_prep(const float* __restrict__ clusters) {
    int i = blockIdx.x * 256 + threadIdx.x;
    if (i < DD * KGC) {
        float v = clusters[i];
        __nv_bfloat16 h = __float2bfloat16(v);
        g_cHi[i] = h;
        g_cLo[i] = __float2bfloat16(v - __bfloat162float(h));
    }
}
// Kernel P2: transpose clusters2 [512][64] -> [64][512]
__global__ void k_prep2(const float* __restrict__ clusters2) {
    int k = blockIdx.x;
    int d = threadIdx.x;
    g_c2T[k * DD + d] = clusters2[d * KK + k];
}

// ---------------------------------------------------------------------------
// Kernel 1: logits GEMM (mma.sync bf16x3) + BN + softmax + a_sum + assignT
// CTA: 256 threads = 8 warps, 4 M-split x 2 N-split. Tile M=128 x N=80,
// K=512 in 8 smem chunks. Register-prefetch pipeline: next stage's x LDGs
// issue before this stage's MMA loop.
// ---------------------------------------------------------------------------
#define L_SAH 0          // x hi:   [128][72] bf16, 144B stride -> 18432B
#define L_SAL 18432      // x lo
#define L_SBH 36864      // c hi:   [64][88] bf16, 176B stride -> 11264B
#define L_SBL 48128      // c lo
#define L_BN  59392      // 240 floats -> 960B
#define L_AS  60352      // 256 floats -> 1024B
#define L_PM  61376      // 256 floats (row-partial max [row][wn])
#define L_PS  62400      // 256 floats (row-partial sum)
#define L_SMEM 63424

__global__ __launch_bounds__(256, 2) void k_logits_mma(
    const float* __restrict__ x,
    const float* __restrict__ bnw, const float* __restrict__ bnb,
    const float* __restrict__ rm, const float* __restrict__ rv)
{
    extern __shared__ __align__(16) char smem[];
    const int tid = threadIdx.x;
    const int lane = tid & 31, w = tid >> 5;
    const int wm = w & 3, wn = w >> 2;           // 4 M-warps x 2 N-warps
    const int b = blockIdx.y, n0 = blockIdx.x * 128;
    const float* xb = x + ((size_t)b * NN + n0) * DD;
    uint32_t sb32 = smem_to_u32(smem);

    float* sScale = (float*)(smem + L_BN);
    float* sRm = sScale + 80;
    float* sBb = sScale + 160;
    if (tid < KGC) {
        sScale[tid] = bnw[tid] * rsqrtf(rv[tid] + 1e-5f);
        sRm[tid] = rm[tid];
        sBb[tid] = bnb[tid];
    }

    float acc[2][5][4];
    #pragma unroll
    for (int mt = 0; mt < 2; mt++)
        #pragma unroll
        for (int nt = 0; nt < 5; nt++)
            #pragma unroll
            for (int e = 0; e < 4; e++) acc[mt][nt][e] = 0.f;

    const int xr_r = tid >> 4, xr_u = tid & 15;  // fixed row/unit per thread
    float4 xr[8];
    #pragma unroll
    for (int j = 0; j < 8; j++)
        xr[j] = *(const float4*)&xb[(size_t)(xr_r + j * 16) * DD + xr_u * 4];

    for (int dt = 0; dt < 8; dt++) {
        // ---- convert & store prefetched x chunk [128 n][64 d] ----
        #pragma unroll
        for (int j = 0; j < 8; j++) {
            uint32_t h0, l0, h1, l1;
            split2(make_float2(xr[j].x, xr[j].y), h0, l0);
            split2(make_float2(xr[j].z, xr[j].w), h1, l1);
            int off = (xr_r + j * 16) * 144 + xr_u * 8;
            *(uint2*)(smem + L_SAH + off) = make_uint2(h0, h1);
            *(uint2*)(smem + L_SAL + off) = make_uint2(l0, l1);
        }
        // ---- stage clusters chunk [64 d][80 c] bf16 (L2-resident) ----
        #pragma unroll
        for (int j = 0; j < 3; j++) {
            int idx = tid + j * 256;
            if (idx < 640) {
                int r = idx / 10, u = idx - r * 10;
                size_t ge = (size_t)(dt * 64 + r) * KGC + u * 8;
                uint4 vh = *(const uint4*)(g_cHi + ge);
                uint4 vl = *(const uint4*)(g_cLo + ge);
                int off = r * 176 + u * 16;
                *(uint4*)(smem + L_SBH + off) = vh;
                *(uint4*)(smem + L_SBL + off) = vl;
            }
        }
        __syncthreads();

        // ---- issue next stage's x LDGs (overlap with MMA below) ----
        if (dt < 7) {
            #pragma unroll
            for (int j = 0; j < 8; j++)
                xr[j] = *(const float4*)&xb[(size_t)(xr_r + j * 16) * DD +
                                            (dt + 1) * 64 + xr_u * 4];
        }

        #pragma unroll
        for (int kt = 0; kt < 4; kt++) {
            uint32_t ah[2][4], al[2][4];
            #pragma unroll
            for (int mt = 0; mt < 2; mt++) {
                uint32_t aoff = (uint32_t)((wm * 32 + mt * 16 + (lane & 15)) * 144 +
                                           (kt * 16 + (lane >> 4) * 8) * 2);
                ldsm_x4(ah[mt], sb32 + L_SAH + aoff);
                ldsm_x4(al[mt], sb32 + L_SAL + aoff);
            }
            uint32_t bh[5][2], bl[5][2];
            #pragma unroll
            for (int p = 0; p < 2; p++) {
                uint32_t t[4];
                uint32_t boff = (uint32_t)((kt * 16 + (lane & 15)) * 176 +
                                           (wn * 40 + p * 16 + (lane >> 4) * 8) * 2);
                ldsm_x4t(t, sb32 + L_SBH + boff);
                bh[2*p][0] = t[0]; bh[2*p][1] = t[1];
                bh[2*p+1][0] = t[2]; bh[2*p+1][1] = t[3];
                ldsm_x4t(t, sb32 + L_SBL + boff);
                bl[2*p][0] = t[0]; bl[2*p][1] = t[1];
                bl[2*p+1][0] = t[2]; bl[2*p+1][1] = t[3];
            }
            {
                uint32_t boff = (uint32_t)((kt * 16 + (lane & 15)) * 176 + (wn * 40 + 32) * 2);
                ldsm_x2t(bh[4], sb32 + L_SBH + boff);
                ldsm_x2t(bl[4], sb32 + L_SBL + boff);
            }
            #pragma unroll
            for (int nt = 0; nt < 5; nt++)
                #pragma unroll
                for (int mt = 0; mt < 2; mt++) {
                    mma_bf16(acc[mt][nt], ah[mt], bh[nt]);
                    mma_bf16(acc[mt][nt], ah[mt], bl[nt]);
                    mma_bf16(acc[mt][nt], al[mt], bh[nt]);
                }
        }
        __syncthreads();
    }

    // ---- BN affine ----
    #pragma unroll
    for (int nt = 0; nt < 5; nt++) {
        int c0 = wn * 40 + nt * 8 + (lane & 3) * 2;
        float s0 = sScale[c0], s1 = sScale[c0 + 1];
        float m0 = sRm[c0],    m1 = sRm[c0 + 1];
        float q0 = sBb[c0],    q1 = sBb[c0 + 1];
        #pragma unroll
        for (int mt = 0; mt < 2; mt++) {
            acc[mt][nt][0] = (acc[mt][nt][0] - m0) * s0 + q0;
            acc[mt][nt][1] = (acc[mt][nt][1] - m1) * s1 + q1;
            acc[mt][nt][2] = (acc[mt][nt][2] - m0) * s0 + q0;
            acc[mt][nt][3] = (acc[mt][nt][3] - m1) * s1 + q1;
        }
    }

    // ---- softmax: rows split across 2 N-warps -> 2-pass smem reduction ----
    float* sPM = (float*)(smem + L_PM);
    float* sPS = (float*)(smem + L_PS);
    float* sOut = (float*)smem;                  // reuse A region: [128][66]

    #pragma unroll
    for (int h = 0; h < 4; h++) {
        int mt = h >> 1, hh = h & 1;
        float mx = -3.4e38f;
        #pragma unroll
        for (int nt = 0; nt < 5; nt++)
            mx = fmaxf(mx, fmaxf(acc[mt][nt][hh * 2], acc[mt][nt][hh * 2 + 1]));
        mx = fmaxf(mx, __shfl_xor_sync(0xffffffffu, mx, 1));
        mx = fmaxf(mx, __shfl_xor_sync(0xffffffffu, mx, 2));
        int row = wm * 32 + mt * 16 + hh * 8 + (lane >> 2);
        if ((lane & 3) == 0) sPM[row * 2 + wn] = mx;
    }
    __syncthreads();
    #pragma unroll
    for (int h = 0; h < 4; h++) {
        int mt = h >> 1, hh = h & 1;
        int row = wm * 32 + mt * 16 + hh * 8 + (lane >> 2);
        float m = fmaxf(sPM[row * 2], sPM[row * 2 + 1]);
        float sum = 0.f;
        #pragma unroll
        for (int nt = 0; nt < 5; nt++) {
            float e0 = __expf(acc[mt][nt][hh * 2] - m);
            float e1 = __expf(acc[mt][nt][hh * 2 + 1] - m);
            acc[mt][nt][hh * 2] = e0;
            acc[mt][nt][hh * 2 + 1] = e1;
            sum += e0 + e1;
        }
        sum += __shfl_xor_sync(0xffffffffu, sum, 1);
        sum += __shfl_xor_sync(0xffffffffu, sum, 2);
        if ((lane & 3) == 0) sPS[row * 2 + wn] = sum;
    }
    __syncthreads();
    const int ntmax = wn ? 3 : 5;                // keep cols < 64 only
    #pragma unroll
    for (int h = 0; h < 4; h++) {
        int mt = h >> 1, hh = h & 1;
        int row = wm * 32 + mt * 16 + hh * 8 + (lane >> 2);
        float inv = 1.0f / (sPS[row * 2] + sPS[row * 2 + 1]);
        #pragma unroll
        for (int nt = 0; nt < 5; nt++) {
            if (nt < ntmax) {
                int col = wn * 40 + nt * 8 + (lane & 3) * 2;
                float2 v = make_float2(acc[mt][nt][hh * 2] * inv,
                                       acc[mt][nt][hh * 2 + 1] * inv);
                *(float2*)&sOut[row * 66 + col] = v;
            }
        }
    }
    __syncthreads();

    // ---- a_sum ----
    float* sAs = (float*)(smem + L_AS);
    {
        int k = tid & 63, q = tid >> 6;
        float s = 0.f;
        #pragma unroll 8
        for (int r = q * 32; r < q * 32 + 32; r++) s += sOut[r * 66 + k];
        sAs[q * 64 + k] = s;
    }
    __syncthreads();
    if (tid < KK)
        atomicAdd(&g_asum[b * KK + tid],
                  sAs[tid] + sAs[64 + tid] + sAs[128 + tid] + sAs[192 + tid]);

    // ---- assignment^T as bf16 hi/lo: coalesced in n ----
    {
        int row = tid & 127, kh = (tid >> 7) * 32;
        __nv_bfloat16* aThi = g_aThi + (size_t)b * KK * NN + n0 + row;
        __nv_bfloat16* aTlo = g_aTlo + (size_t)b * KK * NN + n0 + row;
        #pragma unroll 4
        for (int kk2 = 0; kk2 < 32; kk2++) {
            int k = kh + kk2;
            float v = sOut[row * 66 + k];
            __nv_bfloat16 h = __float2bfloat16(v);
            aThi[(size_t)k * NN] = h;
            aTlo[(size_t)k * NN] = __float2bfloat16(v - __bfloat162float(h));
        }
    }
}

// ---------------------------------------------------------------------------
// Kernel 2: vlad GEMM (mma.sync bf16x3): D[k_clu][d] = assign^T @ x
// CTA: 256 threads (8 warps = 2 M-split x 4 N-split), tile M=64 x N=128 d,
// K(n)=1024 per chunk (2 chunks). Register-prefetch pipeline on x.
// ---------------------------------------------------------------------------
#define V_BXH 0          // x hi: [32][136] bf16, 272B stride -> 8704B
#define V_BXL 8704
#define V_ATH 17408      // aT hi: [64][40] bf16, 80B stride -> 5120B
#define V_ATL 22528      // -> 27648B total

__global__ __launch_bounds__(256, 2) void k_vlad_mma(const float* __restrict__ x)
{
    __shared__ __align__(16) char sm[27648];
    const int tid = threadIdx.x, lane = tid & 31, w = tid >> 5;
    const int wm = w & 1, wn = w >> 1;           // M half (32 k), N quarter (32 d)
    const int b = blockIdx.z, chunk = blockIdx.y, d0 = blockIdx.x * 128;
    const float* xb = x + (size_t)b * NN * DD + d0;
    const __nv_bfloat16* aThi = g_aThi + (size_t)b * KK * NN;
    const __nv_bfloat16* aTlo = g_aTlo + (size_t)b * KK * NN;
    uint32_t sb32 = smem_to_u32(sm);

    float acc[2][4][4];
    #pragma unroll
    for (int mt = 0; mt < 2; mt++)
        #pragma unroll
        for (int nt = 0; nt < 4; nt++)
            #pragma unroll
            for (int e = 0; e < 4; e++) acc[mt][nt][e] = 0.f;

    const int xr_r = tid >> 5, xr_u = tid & 31;  // row (8 per iter), d-quad
    float4 xr[4];
    #pragma unroll
    for (int j = 0; j < 4; j++)
        xr[j] = *(const float4*)&xb[(size_t)(chunk * 1024 + xr_r + j * 8) * DD + xr_u * 4];

    for (int nc = 0; nc < 32; nc++) {
        const int nbase = chunk * 1024 + nc * 32;
        // ---- convert & store prefetched x tile [32 n][128 d] ----
        #pragma unroll
        for (int j = 0; j < 4; j++) {
            uint32_t h0, l0, h1, l1;
            split2(make_float2(xr[j].x, xr[j].y), h0, l0);
            split2(make_float2(xr[j].z, xr[j].w), h1, l1);
            int off = (xr_r + j * 8) * 272 + xr_u * 8;
            *(uint2*)(sm + V_BXH + off) = make_uint2(h0, h1);
            *(uint2*)(sm + V_BXL + off) = make_uint2(l0, l1);
        }
        // ---- aT tile [64 k][32 n] bf16 hi/lo (mostly L2) ----
        {
            int r = tid >> 2, u = tid & 3;
            size_t ge = (size_t)r * NN + nbase + u * 8;
            uint4 vh = *(const uint4*)(aThi + ge);
            uint4 vl = *(const uint4*)(aTlo + ge);
            int off = r * 80 + u * 16;
            *(uint4*)(sm + V_ATH + off) = vh;
            *(uint4*)(sm + V_ATL + off) = vl;
        }
        __syncthreads();

        // ---- issue next tile's x LDGs (overlap with MMA below) ----
        if (nc < 31) {
            #pragma unroll
            for (int j = 0; j < 4; j++)
                xr[j] = *(const float4*)&xb[(size_t)(nbase + 32 + xr_r + j * 8) * DD +
                                            xr_u * 4];
        }

        #pragma unroll
        for (int kt = 0; kt < 2; kt++) {
            uint32_t ah[2][4], al[2][4];
            #pragma unroll
            for (int mt = 0; mt < 2; mt++) {
                uint32_t aoff = (uint32_t)((wm * 32 + mt * 16 + (lane & 15)) * 80 +
                                           (kt * 16 + (lane >> 4) * 8) * 2);
                ldsm_x4(ah[mt], sb32 + V_ATH + aoff);
                ldsm_x4(al[mt], sb32 + V_ATL + aoff);
            }
            uint32_t bh[4][2], bl[4][2];
            #pragma unroll
            for (int p = 0; p < 2; p++) {
                uint32_t t[4];
                uint32_t boff = (uint32_t)((kt * 16 + (lane & 15)) * 272 +
                                           (wn * 32 + p * 16 + (lane >> 4) * 8) * 2);
                ldsm_x4t(t, sb32 + V_BXH + boff);
                bh[2*p][0] = t[0]; bh[2*p][1] = t[1];
                bh[2*p+1][0] = t[2]; bh[2*p+1][1] = t[3];
                ldsm_x4t(t, sb32 + V_BXL + boff);
                bl[2*p][0] = t[0]; bl[2*p][1] = t[1];
                bl[2*p+1][0] = t[2]; bl[2*p+1][1] = t[3];
            }
            #pragma unroll
            for (int nt = 0; nt < 4; nt++)
                #pragma unroll
                for (int mt = 0; mt < 2; mt++) {
                    mma_bf16(acc[mt][nt], ah[mt], bh[nt]);
                    mma_bf16(acc[mt][nt], ah[mt], bl[nt]);
                    mma_bf16(acc[mt][nt], al[mt], bh[nt]);
                }
        }
        __syncthreads();
    }

    float* vp = g_vpart[chunk] + (size_t)b * KK * DD;
    #pragma unroll
    for (int mt = 0; mt < 2; mt++) {
        int k0 = wm * 32 + mt * 16 + (lane >> 2);
        #pragma unroll
        for (int nt = 0; nt < 4; nt++) {
            int d = d0 + wn * 32 + nt * 8 + (lane & 3) * 2;
            *(float2*)&vp[(size_t)k0 * DD + d]       = make_float2(acc[mt][nt][0], acc[mt][nt][1]);
            *(float2*)&vp[(size_t)(k0 + 8) * DD + d] = make_float2(acc[mt][nt][2], acc[mt][nt][3]);
        }
    }
}

// ---------------------------------------------------------------------------
// Kernel 3: finisher — sum partials, subtract a_sum*clusters2, transpose to
// out[b][d][k], per-(b,k) norm^2. Grid (8 dgroups, B), 256 threads.
// ---------------------------------------------------------------------------
__global__ __launch_bounds__(256) void k_fin(float* __restrict__ out)
{
    __shared__ float sT[64][66];
    __shared__ float sN[64];
    const int b = blockIdx.y, dg = blockIdx.x;
    const int lane = threadIdx.x & 31, w = threadIdx.x >> 5;
    const float* vp0 = g_vpart[0] + (size_t)b * KK * DD;
    const float* vp1 = g_vpart[1] + (size_t)b * KK * DD;

    #pragma unroll
    for (int kr = 0; kr < 8; kr++) {
        int k = w * 8 + kr;
        float as = g_asum[b * KK + k];
        int d = dg * 64 + lane;
        float v0 = vp0[(size_t)k * DD + d]      + vp1[(size_t)k * DD + d]
                 - as * g_c2T[k * DD + d];
        float v1 = vp0[(size_t)k * DD + d + 32] + vp1[(size_t)k * DD + d + 32]
                 - as * g_c2T[k * DD + d + 32];
        sT[lane][k]      = v0;
        sT[lane + 32][k] = v1;
        float n2 = v0 * v0 + v1 * v1;
        #pragma unroll
        for (int o = 16; o >= 1; o >>= 1) n2 += __shfl_xor_sync(0xffffffffu, n2, o);
        if (lane == 0) sN[k] = n2;
    }
    __syncthreads();
    if (threadIdx.x < KK)
        atomicAdd(&g_norm2[b * KK + threadIdx.x], sN[threadIdx.x]);
    #pragma unroll
    for (int j = 0; j < 16; j++) {
        int idx = threadIdx.x + j * 256;
        int d = idx >> 6, k = idx & 63;
        out[((size_t)b * DD + dg * 64 + d) * KK + k] = sT[d][k];
    }
}

// ---------------------------------------------------------------------------
// Kernel 4: per-(b,k) combined scale
// ---------------------------------------------------------------------------
__global__ void k_colscale() {
    int b = blockIdx.x;
    int k = threadIdx.x;
    float n2 = g_norm2[b * KK + k];
    float nr = sqrtf(n2);
    float inv = 1.0f / fmaxf(nr, 1e-12f);
    float c = n2 * inv * inv;
    __shared__ float sh[2];
    #pragma unroll
    for (int o = 16; o >= 1; o >>= 1) c += __shfl_xor_sync(0xffffffffu, c, o);
    if ((threadIdx.x & 31) == 0) sh[threadIdx.x >> 5] = c;
    __syncthreads();
    float tot = sqrtf(sh[0] + sh[1]);
    float invt = 1.0f / fmaxf(tot, 1e-12f);
    g_scale[b * KK + k] = inv * invt;
}

// ---------------------------------------------------------------------------
// Kernel 5: in-place scale of d_out
// ---------------------------------------------------------------------------
__global__ void k_out(float* __restrict__ out) {
    int i = blockIdx.x * 256 + threadIdx.x;
    int b = i >> 15;
    int k = i & 63;
    out[i] = out[i] * g_scale[(b << 6) + k];
}

// ---------------------------------------------------------------------------
extern "C" void kernel_launch(void* const* d_in, const int* in_sizes, int n_in,
                              void* d_out, int out_size) {
    const float* x         = (const float*)d_in[0];
    const float* clusters  = (const float*)d_in[1];
    const float* clusters2 = (const float*)d_in[2];
    const float* bnw       = (const float*)d_in[3];
    const float* bnb       = (const float*)d_in[4];
    const float* rm        = (const float*)d_in[5];
    const float* rv        = (const float*)d_in[6];
    float* out = (float*)d_out;

    cudaFuncSetAttribute(k_logits_mma, cudaFuncAttributeMaxDynamicSharedMemorySize, L_SMEM);

    k_zero<<<(BB * KK + 255) / 256, 256>>>();
    k_prep<<<(DD * KGC + 255) / 256, 256>>>(clusters);
    k_prep2<<<KK, DD>>>(clusters2);
    dim3 g1(NN / 128, BB);
    k_logits_mma<<<g1, 256, L_SMEM>>>(x, bnw, bnb, rm, rv);
    dim3 g2(DD / 128, 2, BB);
    k_vlad_mma<<<g2, 256>>>(x);
    dim3 g3(8, BB);
    k_fin<<<g3, 256>>>(out);
    k_colscale<<<BB, KK>>>();
    k_out<<<(BB * DD * KK) / 256, 256>>>(out);
}

// round 10
// speedup vs baseline: 4.5861x; 1.1319x over previous
#include <cuda_runtime.h>
#include <cuda_bf16.h>
#include <cstdint>

#define BB 64
#define NN 2048
#define DD 512
#define KK 64
#define KGC 80

// Scratch (device globals — no allocation allowed)
__device__ __nv_bfloat16 g_aThi[(size_t)BB * KK * NN];   // assignment^T hi [b][k][n]
__device__ __nv_bfloat16 g_aTlo[(size_t)BB * KK * NN];   // assignment^T lo
__device__ float g_vpart[2][(size_t)BB * KK * DD];       // vlad partials [chunk][b][k][d]
__device__ float g_asum[BB * KK];
__device__ float g_norm2[BB * KK];
__device__ float g_scale[BB * KK];
__device__ __nv_bfloat16 g_cHi[DD * KGC];                // clusters hi split [d][c]
__device__ __nv_bfloat16 g_cLo[DD * KGC];                // clusters lo split
__device__ float g_c2T[KK * DD];                         // clusters2^T [k][d]

// ===================== mma.sync / ldmatrix helpers =====================
__device__ __forceinline__ uint32_t smem_to_u32(const void* p) {
    uint32_t a;
    asm("{ .reg .u64 t; cvta.to.shared.u64 t, %1; cvt.u32.u64 %0, t; }" : "=r"(a) : "l"(p));
    return a;
}
__device__ __forceinline__ void mma_bf16(float* c, const uint32_t* a, const uint32_t* b) {
    asm volatile("mma.sync.aligned.m16n8k16.row.col.f32.bf16.bf16.f32 "
        "{%0,%1,%2,%3}, {%4,%5,%6,%7}, {%8,%9}, {%0,%1,%2,%3};"
        : "+f"(c[0]), "+f"(c[1]), "+f"(c[2]), "+f"(c[3])
        : "r"(a[0]), "r"(a[1]), "r"(a[2]), "r"(a[3]), "r"(b[0]), "r"(b[1]));
}
__device__ __forceinline__ void ldsm_x4(uint32_t* r, uint32_t addr) {
    asm volatile("ldmatrix.sync.aligned.m8n8.x4.shared.b16 {%0,%1,%2,%3}, [%4];"
        : "=r"(r[0]), "=r"(r[1]), "=r"(r[2]), "=r"(r[3]) : "r"(addr));
}
__device__ __forceinline__ void ldsm_x4t(uint32_t* r, uint32_t addr) {
    asm volatile("ldmatrix.sync.aligned.m8n8.x4.trans.shared.b16 {%0,%1,%2,%3}, [%4];"
        : "=r"(r[0]), "=r"(r[1]), "=r"(r[2]), "=r"(r[3]) : "r"(addr));
}
__device__ __forceinline__ void ldsm_x2t(uint32_t* r, uint32_t addr) {
    asm volatile("ldmatrix.sync.aligned.m8n8.x2.trans.shared.b16 {%0,%1}, [%2];"
        : "=r"(r[0]), "=r"(r[1]) : "r"(addr));
}
__device__ __forceinline__ void split2(float2 v, uint32_t& hi, uint32_t& lo) {
    __nv_bfloat162 h = __float22bfloat162_rn(v);
    float2 hf = __bfloat1622float2(h);
    __nv_bfloat162 l = __float22bfloat162_rn(make_float2(v.x - hf.x, v.y - hf.y));
    hi = *(uint32_t*)&h;
    lo = *(uint32_t*)&l;
}

// ---------------------------------------------------------------------------
// Kernel 0: zero accumulators
// ---------------------------------------------------------------------------
__global__ void k_zero() {
    int i = blockIdx.x * 256 + threadIdx.x;
    if (i < BB * KK) { g_asum[i] = 0.0f; g_norm2[i] = 0.0f; }
}

// ---------------------------------------------------------------------------
// Kernel P1: split clusters [512][80] into bf16 hi/lo
// ---------------------------------------------------------------------------
__global__ void k_prep(const float* __restrict__ clusters) {
    int i = blockIdx.x * 256 + threadIdx.x;
    if (i < DD * KGC) {
        float v = clusters[i];
        __nv_bfloat16 h = __float2bfloat16(v);
        g_cHi[i] = h;
        g_cLo[i] = __float2bfloat16(v - __bfloat162float(h));
    }
}
// Kernel P2: transpose clusters2 [512][64] -> [64][512]
__global__ void k_prep2(const float* __restrict__ clusters2) {
    int k = blockIdx.x;
    int d = threadIdx.x;
    g_c2T[k * DD + d] = clusters2[d * KK + k];
}

// ---------------------------------------------------------------------------
// Kernel 1: logits GEMM (mma.sync bf16x3) + BN + softmax + a_sum + assignT
// CTA: 256 threads = 8 warps, 4 M-split x 2 N-split. Tile M=128 x N=80,
// K=512 in 16 chunks of 32 d, DOUBLE-BUFFERED smem, 1 sync/stage, full
// register prefetch. A-tile stride 80 B (16-aligned for ldmatrix).
// ---------------------------------------------------------------------------
// per-buffer (31744 B): AH [128][40]bf16(80B stride) @0, AL @10240,
//                       BH [32][88]bf16(176B stride) @20480, BL @26112
#define LB_AH 0
#define LB_AL 10240
#define LB_BH 20480
#define LB_BL 26112
#define LB_SZ 31744
#define L_BN  63488      // 240 floats
#define L_AS  64448      // 256 floats
#define L_PM  65472      // 256 floats
#define L_PS  66496      // 256 floats
#define L_SMEM 67520

__global__ __launch_bounds__(256, 2) void k_logits_mma(
    const float* __restrict__ x,
    const float* __restrict__ bnw, const float* __restrict__ bnb,
    const float* __restrict__ rm, const float* __restrict__ rv)
{
    extern __shared__ __align__(16) char smem[];
    const int tid = threadIdx.x;
    const int lane = tid & 31, w = tid >> 5;
    const int wm = w & 3, wn = w >> 2;           // 4 M-warps x 2 N-warps
    const int b = blockIdx.y, n0 = blockIdx.x * 128;
    const float* xb = x + ((size_t)b * NN + n0) * DD;
    uint32_t sb32 = smem_to_u32(smem);

    float* sScale = (float*)(smem + L_BN);
    float* sRm = sScale + 80;
    float* sBb = sScale + 160;
    if (tid < KGC) {
        sScale[tid] = bnw[tid] * rsqrtf(rv[tid] + 1e-5f);
        sRm[tid] = rm[tid];
        sBb[tid] = bnb[tid];
    }

    float acc[2][5][4];
    #pragma unroll
    for (int mt = 0; mt < 2; mt++)
        #pragma unroll
        for (int nt = 0; nt < 5; nt++)
            #pragma unroll
            for (int e = 0; e < 4; e++) acc[mt][nt][e] = 0.f;

    // prefetch lanes: x rows xr_r + j*32 (j=0..3), 8 float4 per 32-d row
    const int xr_r = tid >> 3, xr_u = tid & 7;
    // B prefetch: 320 16B-units per half; idx = tid (+256 predicated)
    const int br0 = tid / 10, bu0 = tid - br0 * 10;
    const int bidx1 = tid + 256;
    const int br1 = bidx1 / 10, bu1 = bidx1 - br1 * 10;
    const bool bp1 = bidx1 < 320;

    float4 xr[4];
    uint4 bhr[2], blr[2];

    // ---- prefetch stage 0 ----
    #pragma unroll
    for (int j = 0; j < 4; j++)
        xr[j] = *(const float4*)&xb[(size_t)(xr_r + j * 32) * DD + xr_u * 4];
    bhr[0] = *(const uint4*)(g_cHi + (size_t)br0 * KGC + bu0 * 8);
    blr[0] = *(const uint4*)(g_cLo + (size_t)br0 * KGC + bu0 * 8);
    if (bp1) {
        bhr[1] = *(const uint4*)(g_cHi + (size_t)br1 * KGC + bu1 * 8);
        blr[1] = *(const uint4*)(g_cLo + (size_t)br1 * KGC + bu1 * 8);
    }

    for (int dt = 0; dt < 16; dt++) {
        char* buf = smem + (dt & 1) * LB_SZ;
        // ---- STS prefetched x (convert) and B ----
        #pragma unroll
        for (int j = 0; j < 4; j++) {
            uint32_t h0, l0, h1, l1;
            split2(make_float2(xr[j].x, xr[j].y), h0, l0);
            split2(make_float2(xr[j].z, xr[j].w), h1, l1);
            int off = (xr_r + j * 32) * 80 + xr_u * 8;
            *(uint2*)(buf + LB_AH + off) = make_uint2(h0, h1);
            *(uint2*)(buf + LB_AL + off) = make_uint2(l0, l1);
        }
        {
            int off0 = br0 * 176 + bu0 * 16;
            *(uint4*)(buf + LB_BH + off0) = bhr[0];
            *(uint4*)(buf + LB_BL + off0) = blr[0];
            if (bp1) {
                int off1 = br1 * 176 + bu1 * 16;
                *(uint4*)(buf + LB_BH + off1) = bhr[1];
                *(uint4*)(buf + LB_BL + off1) = blr[1];
            }
        }
        // ---- prefetch stage dt+1 ----
        if (dt < 15) {
            #pragma unroll
            for (int j = 0; j < 4; j++)
                xr[j] = *(const float4*)&xb[(size_t)(xr_r + j * 32) * DD +
                                            (dt + 1) * 32 + xr_u * 4];
            size_t gb = (size_t)(dt + 1) * 32 * KGC;
            bhr[0] = *(const uint4*)(g_cHi + gb + (size_t)br0 * KGC + bu0 * 8);
            blr[0] = *(const uint4*)(g_cLo + gb + (size_t)br0 * KGC + bu0 * 8);
            if (bp1) {
                bhr[1] = *(const uint4*)(g_cHi + gb + (size_t)br1 * KGC + bu1 * 8);
                blr[1] = *(const uint4*)(g_cLo + gb + (size_t)br1 * KGC + bu1 * 8);
            }
        }
        __syncthreads();

        uint32_t bufo = sb32 + (uint32_t)((dt & 1) * LB_SZ);
        #pragma unroll
        for (int kt = 0; kt < 2; kt++) {
            uint32_t ah[2][4], al[2][4];
            #pragma unroll
            for (int mt = 0; mt < 2; mt++) {
                uint32_t aoff = (uint32_t)((wm * 32 + mt * 16 + (lane & 15)) * 80 +
                                           (kt * 16 + (lane >> 4) * 8) * 2);
                ldsm_x4(ah[mt], bufo + LB_AH + aoff);
                ldsm_x4(al[mt], bufo + LB_AL + aoff);
            }
            uint32_t bh[5][2], bl[5][2];
            #pragma unroll
            for (int p = 0; p < 2; p++) {
                uint32_t t[4];
                uint32_t boff = (uint32_t)((kt * 16 + (lane & 15)) * 176 +
                                           (wn * 40 + p * 16 + (lane >> 4) * 8) * 2);
                ldsm_x4t(t, bufo + LB_BH + boff);
                bh[2*p][0] = t[0]; bh[2*p][1] = t[1];
                bh[2*p+1][0] = t[2]; bh[2*p+1][1] = t[3];
                ldsm_x4t(t, bufo + LB_BL + boff);
                bl[2*p][0] = t[0]; bl[2*p][1] = t[1];
                bl[2*p+1][0] = t[2]; bl[2*p+1][1] = t[3];
            }
            {
                uint32_t boff = (uint32_t)((kt * 16 + (lane & 15)) * 176 + (wn * 40 + 32) * 2);
                ldsm_x2t(bh[4], bufo + LB_BH + boff);
                ldsm_x2t(bl[4], bufo + LB_BL + boff);
            }
            #pragma unroll
            for (int nt = 0; nt < 5; nt++)
                #pragma unroll
                for (int mt = 0; mt < 2; mt++) {
                    mma_bf16(acc[mt][nt], ah[mt], bh[nt]);
                    mma_bf16(acc[mt][nt], ah[mt], bl[nt]);
                    mma_bf16(acc[mt][nt], al[mt], bh[nt]);
                }
        }
    }
    __syncthreads();

    // ---- BN affine ----
    #pragma unroll
    for (int nt = 0; nt < 5; nt++) {
        int c0 = wn * 40 + nt * 8 + (lane & 3) * 2;
        float s0 = sScale[c0], s1 = sScale[c0 + 1];
        float m0 = sRm[c0],    m1 = sRm[c0 + 1];
        float q0 = sBb[c0],    q1 = sBb[c0 + 1];
        #pragma unroll
        for (int mt = 0; mt < 2; mt++) {
            acc[mt][nt][0] = (acc[mt][nt][0] - m0) * s0 + q0;
            acc[mt][nt][1] = (acc[mt][nt][1] - m1) * s1 + q1;
            acc[mt][nt][2] = (acc[mt][nt][2] - m0) * s0 + q0;
            acc[mt][nt][3] = (acc[mt][nt][3] - m1) * s1 + q1;
        }
    }

    // ---- softmax: rows split across 2 N-warps -> 2-pass smem reduction ----
    float* sPM = (float*)(smem + L_PM);
    float* sPS = (float*)(smem + L_PS);
    float* sOut = (float*)smem;                  // reuse buffers: [128][66]

    #pragma unroll
    for (int h = 0; h < 4; h++) {
        int mt = h >> 1, hh = h & 1;
        float mx = -3.4e38f;
        #pragma unroll
        for (int nt = 0; nt < 5; nt++)
            mx = fmaxf(mx, fmaxf(acc[mt][nt][hh * 2], acc[mt][nt][hh * 2 + 1]));
        mx = fmaxf(mx, __shfl_xor_sync(0xffffffffu, mx, 1));
        mx = fmaxf(mx, __shfl_xor_sync(0xffffffffu, mx, 2));
        int row = wm * 32 + mt * 16 + hh * 8 + (lane >> 2);
        if ((lane & 3) == 0) sPM[row * 2 + wn] = mx;
    }
    __syncthreads();
    #pragma unroll
    for (int h = 0; h < 4; h++) {
        int mt = h >> 1, hh = h & 1;
        int row = wm * 32 + mt * 16 + hh * 8 + (lane >> 2);
        float m = fmaxf(sPM[row * 2], sPM[row * 2 + 1]);
        float sum = 0.f;
        #pragma unroll
        for (int nt = 0; nt < 5; nt++) {
            float e0 = __expf(acc[mt][nt][hh * 2] - m);
            float e1 = __expf(acc[mt][nt][hh * 2 + 1] - m);
            acc[mt][nt][hh * 2] = e0;
            acc[mt][nt][hh * 2 + 1] = e1;
            sum += e0 + e1;
        }
        sum += __shfl_xor_sync(0xffffffffu, sum, 1);
        sum += __shfl_xor_sync(0xffffffffu, sum, 2);
        if ((lane & 3) == 0) sPS[row * 2 + wn] = sum;
    }
    __syncthreads();
    const int ntmax = wn ? 3 : 5;                // keep cols < 64 only
    #pragma unroll
    for (int h = 0; h < 4; h++) {
        int mt = h >> 1, hh = h & 1;
        int row = wm * 32 + mt * 16 + hh * 8 + (lane >> 2);
        float inv = 1.0f / (sPS[row * 2] + sPS[row * 2 + 1]);
        #pragma unroll
        for (int nt = 0; nt < 5; nt++) {
            if (nt < ntmax) {
                int col = wn * 40 + nt * 8 + (lane & 3) * 2;
                float2 v = make_float2(acc[mt][nt][hh * 2] * inv,
                                       acc[mt][nt][hh * 2 + 1] * inv);
                *(float2*)&sOut[row * 66 + col] = v;
            }
        }
    }
    __syncthreads();

    // ---- a_sum ----
    float* sAs = (float*)(smem + L_AS);
    {
        int k = tid & 63, q = tid >> 6;
        float s = 0.f;
        #pragma unroll 8
        for (int r = q * 32; r < q * 32 + 32; r++) s += sOut[r * 66 + k];
        sAs[q * 64 + k] = s;
    }
    __syncthreads();
    if (tid < KK)
        atomicAdd(&g_asum[b * KK + tid],
                  sAs[tid] + sAs[64 + tid] + sAs[128 + tid] + sAs[192 + tid]);

    // ---- assignment^T as bf16 hi/lo: coalesced in n ----
    {
        int row = tid & 127, kh = (tid >> 7) * 32;
        __nv_bfloat16* aThi = g_aThi + (size_t)b * KK * NN + n0 + row;
        __nv_bfloat16* aTlo = g_aTlo + (size_t)b * KK * NN + n0 + row;
        #pragma unroll 4
        for (int kk2 = 0; kk2 < 32; kk2++) {
            int k = kh + kk2;
            float v = sOut[row * 66 + k];
            __nv_bfloat16 h = __float2bfloat16(v);
            aThi[(size_t)k * NN] = h;
            aTlo[(size_t)k * NN] = __float2bfloat16(v - __bfloat162float(h));
        }
    }
}

// ---------------------------------------------------------------------------
// Kernel 2: vlad GEMM (mma.sync bf16x3): D[k_clu][d] = assign^T @ x
// CTA: 256 threads (8 warps = 2 M-split x 4 N-split), tile M=64 x N=128 d,
// K(n)=1024 per chunk (2 chunks). DOUBLE-BUFFERED smem, 1 sync/stage.
// ---------------------------------------------------------------------------
// per-buffer (27648 B): BXH [32][136] @0, BXL @8704, ATH [64][40] @17408,
//                       ATL @22528
#define VB_XH 0
#define VB_XL 8704
#define VB_AH 17408
#define VB_AL 22528
#define VB_SZ 27648

__global__ __launch_bounds__(256, 2) void k_vlad_mma(const float* __restrict__ x)
{
    __shared__ __align__(16) char sm[2 * VB_SZ];
    const int tid = threadIdx.x, lane = tid & 31, w = tid >> 5;
    const int wm = w & 1, wn = w >> 1;           // M half (32 k), N quarter (32 d)
    const int b = blockIdx.z, chunk = blockIdx.y, d0 = blockIdx.x * 128;
    const float* xb = x + (size_t)b * NN * DD + d0;
    const __nv_bfloat16* aThi = g_aThi + (size_t)b * KK * NN;
    const __nv_bfloat16* aTlo = g_aTlo + (size_t)b * KK * NN;
    uint32_t sb32 = smem_to_u32(sm);

    float acc[2][4][4];
    #pragma unroll
    for (int mt = 0; mt < 2; mt++)
        #pragma unroll
        for (int nt = 0; nt < 4; nt++)
            #pragma unroll
            for (int e = 0; e < 4; e++) acc[mt][nt][e] = 0.f;

    const int xr_r = tid >> 5, xr_u = tid & 31;  // x rows (8/iter), d-quad
    const int ar_r = tid >> 2, ar_u = tid & 3;   // aT row, n-unit

    float4 xr[4];
    uint4 arh, arl;

    // ---- prefetch stage 0 ----
    {
        const int nbase = chunk * 1024;
        #pragma unroll
        for (int j = 0; j < 4; j++)
            xr[j] = *(const float4*)&xb[(size_t)(nbase + xr_r + j * 8) * DD + xr_u * 4];
        size_t ge = (size_t)ar_r * NN + nbase + ar_u * 8;
        arh = *(const uint4*)(aThi + ge);
        arl = *(const uint4*)(aTlo + ge);
    }

    for (int nc = 0; nc < 32; nc++) {
        char* buf = sm + (nc & 1) * VB_SZ;
        // ---- STS prefetched tiles ----
        #pragma unroll
        for (int j = 0; j < 4; j++) {
            uint32_t h0, l0, h1, l1;
            split2(make_float2(xr[j].x, xr[j].y), h0, l0);
            split2(make_float2(xr[j].z, xr[j].w), h1, l1);
            int off = (xr_r + j * 8) * 272 + xr_u * 8;
            *(uint2*)(buf + VB_XH + off) = make_uint2(h0, h1);
            *(uint2*)(buf + VB_XL + off) = make_uint2(l0, l1);
        }
        {
            int off = ar_r * 80 + ar_u * 16;
            *(uint4*)(buf + VB_AH + off) = arh;
            *(uint4*)(buf + VB_AL + off) = arl;
        }
        // ---- prefetch stage nc+1 ----
        if (nc < 31) {
            const int nbase = chunk * 1024 + (nc + 1) * 32;
            #pragma unroll
            for (int j = 0; j < 4; j++)
                xr[j] = *(const float4*)&xb[(size_t)(nbase + xr_r + j * 8) * DD + xr_u * 4];
            size_t ge = (size_t)ar_r * NN + nbase + ar_u * 8;
            arh = *(const uint4*)(aThi + ge);
            arl = *(const uint4*)(aTlo + ge);
        }
        __syncthreads();

        uint32_t bufo = sb32 + (uint32_t)((nc & 1) * VB_SZ);
        #pragma unroll
        for (int kt = 0; kt < 2; kt++) {
            uint32_t ah[2][4], al[2][4];
            #pragma unroll
            for (int mt = 0; mt < 2; mt++) {
                uint32_t aoff = (uint32_t)((wm * 32 + mt * 16 + (lane & 15)) * 80 +
                                           (kt * 16 + (lane >> 4) * 8) * 2);
                ldsm_x4(ah[mt], bufo + VB_AH + aoff);
                ldsm_x4(al[mt], bufo + VB_AL + aoff);
            }
            uint32_t bh[4][2], bl[4][2];
            #pragma unroll
            for (int p = 0; p < 2; p++) {
                uint32_t t[4];
                uint32_t boff = (uint32_t)((kt * 16 + (lane & 15)) * 272 +
                                           (wn * 32 + p * 16 + (lane >> 4) * 8) * 2);
                ldsm_x4t(t, bufo + VB_XH + boff);
                bh[2*p][0] = t[0]; bh[2*p][1] = t[1];
                bh[2*p+1][0] = t[2]; bh[2*p+1][1] = t[3];
                ldsm_x4t(t, bufo + VB_XL + boff);
                bl[2*p][0] = t[0]; bl[2*p][1] = t[1];
                bl[2*p+1][0] = t[2]; bl[2*p+1][1] = t[3];
            }
            #pragma unroll
            for (int nt = 0; nt < 4; nt++)
                #pragma unroll
                for (int mt = 0; mt < 2; mt++) {
                    mma_bf16(acc[mt][nt], ah[mt], bh[nt]);
                    mma_bf16(acc[mt][nt], ah[mt], bl[nt]);
                    mma_bf16(acc[mt][nt], al[mt], bh[nt]);
                }
        }
    }

    float* vp = g_vpart[chunk] + (size_t)b * KK * DD;
    #pragma unroll
    for (int mt = 0; mt < 2; mt++) {
        int k0 = wm * 32 + mt * 16 + (lane >> 2);
        #pragma unroll
        for (int nt = 0; nt < 4; nt++) {
            int d = d0 + wn * 32 + nt * 8 + (lane & 3) * 2;
            *(float2*)&vp[(size_t)k0 * DD + d]       = make_float2(acc[mt][nt][0], acc[mt][nt][1]);
            *(float2*)&vp[(size_t)(k0 + 8) * DD + d] = make_float2(acc[mt][nt][2], acc[mt][nt][3]);
        }
    }
}

// ---------------------------------------------------------------------------
// Kernel 3: finisher — sum partials, subtract a_sum*clusters2, transpose to
// out[b][d][k], per-(b,k) norm^2. Grid (8 dgroups, B), 256 threads.
// ---------------------------------------------------------------------------
__global__ __launch_bounds__(256) void k_fin(float* __restrict__ out)
{
    __shared__ float sT[64][66];
    __shared__ float sN[64];
    const int b = blockIdx.y, dg = blockIdx.x;
    const int lane = threadIdx.x & 31, w = threadIdx.x >> 5;
    const float* vp0 = g_vpart[0] + (size_t)b * KK * DD;
    const float* vp1 = g_vpart[1] + (size_t)b * KK * DD;

    #pragma unroll
    for (int kr = 0; kr < 8; kr++) {
        int k = w * 8 + kr;
        float as = g_asum[b * KK + k];
        int d = dg * 64 + lane;
        float v0 = vp0[(size_t)k * DD + d]      + vp1[(size_t)k * DD + d]
                 - as * g_c2T[k * DD + d];
        float v1 = vp0[(size_t)k * DD + d + 32] + vp1[(size_t)k * DD + d + 32]
                 - as * g_c2T[k * DD + d + 32];
        sT[lane][k]      = v0;
        sT[lane + 32][k] = v1;
        float n2 = v0 * v0 + v1 * v1;
        #pragma unroll
        for (int o = 16; o >= 1; o >>= 1) n2 += __shfl_xor_sync(0xffffffffu, n2, o);
        if (lane == 0) sN[k] = n2;
    }
    __syncthreads();
    if (threadIdx.x < KK)
        atomicAdd(&g_norm2[b * KK + threadIdx.x], sN[threadIdx.x]);
    #pragma unroll
    for (int j = 0; j < 16; j++) {
        int idx = threadIdx.x + j * 256;
        int d = idx >> 6, k = idx & 63;
        out[((size_t)b * DD + dg * 64 + d) * KK + k] = sT[d][k];
    }
}

// ---------------------------------------------------------------------------
// Kernel 4: per-(b,k) combined scale
// ---------------------------------------------------------------------------
__global__ void k_colscale() {
    int b = blockIdx.x;
    int k = threadIdx.x;
    float n2 = g_norm2[b * KK + k];
    float nr = sqrtf(n2);
    float inv = 1.0f / fmaxf(nr, 1e-12f);
    float c = n2 * inv * inv;
    __shared__ float sh[2];
    #pragma unroll
    for (int o = 16; o >= 1; o >>= 1) c += __shfl_xor_sync(0xffffffffu, c, o);
    if ((threadIdx.x & 31) == 0) sh[threadIdx.x >> 5] = c;
    __syncthreads();
    float tot = sqrtf(sh[0] + sh[1]);
    float invt = 1.0f / fmaxf(tot, 1e-12f);
    g_scale[b * KK + k] = inv * invt;
}

// ---------------------------------------------------------------------------
// Kernel 5: in-place scale of d_out
// ---------------------------------------------------------------------------
__global__ void k_out(float* __restrict__ out) {
    int i = blockIdx.x * 256 + threadIdx.x;
    int b = i >> 15;
    int k = i & 63;
    out[i] = out[i] * g_scale[(b << 6) + k];
}

// ---------------------------------------------------------------------------
extern "C" void kernel_launch(void* const* d_in, const int* in_sizes, int n_in,
                              void* d_out, int out_size) {
    const float* x         = (const float*)d_in[0];
    const float* clusters  = (const float*)d_in[1];
    const float* clusters2 = (const float*)d_in[2];
    const float* bnw       = (const float*)d_in[3];
    const float* bnb       = (const float*)d_in[4];
    const float* rm        = (const float*)d_in[5];
    const float* rv        = (const float*)d_in[6];
    float* out = (float*)d_out;

    cudaFuncSetAttribute(k_logits_mma, cudaFuncAttributeMaxDynamicSharedMemorySize, L_SMEM);

    k_zero<<<(BB * KK + 255) / 256, 256>>>();
    k_prep<<<(DD * KGC + 255) / 256, 256>>>(clusters);
    k_prep2<<<KK, DD>>>(clusters2);
    dim3 g1(NN / 128, BB);
    k_logits_mma<<<g1, 256, L_SMEM>>>(x, bnw, bnb, rm, rv);
    dim3 g2(DD / 128, 2, BB);
    k_vlad_mma<<<g2, 256>>>(x);
    dim3 g3(8, BB);
    k_fin<<<g3, 256>>>(out);
    k_colscale<<<BB, KK>>>();
    k_out<<<(BB * DD * KK) / 256, 256>>>(out);
}